// round 1
// baseline (speedup 1.0000x reference)
#include <cuda_runtime.h>
#include <math.h>

// Problem constants
#define BATCH 2
#define SEQ   2048
#define DMODEL 1024
#define NHEAD 16
#define DHEAD 64
#define MROWS (BATCH * SEQ)   // 4096

// Scratch (allocation-free rule: __device__ globals)
__device__ float g_Q[MROWS * DMODEL];
__device__ float g_K[MROWS * DMODEL];
__device__ float g_V[MROWS * DMODEL];
__device__ float g_AO[MROWS * DMODEL];

// ---------------------------------------------------------------------------
// GEMM: C[4096,1024] = relu(A[4096,1024] @ W[1024,1024] + bias[1024])
// 64x64 tile, BK=16, 256 threads, 4x4 per-thread microtile.
// ---------------------------------------------------------------------------
__global__ __launch_bounds__(256) void gemm_bias_relu(
    const float* __restrict__ A, const float* __restrict__ W,
    const float* __restrict__ bias, float* __restrict__ C)
{
    const int N = 1024, K = 1024;
    __shared__ float As[16][64];   // [k][m]
    __shared__ float Bs[16][64];   // [k][n]

    int tid = threadIdx.x;
    int tx = tid & 15;          // 0..15 -> n
    int ty = tid >> 4;          // 0..15 -> m
    int rowBase = blockIdx.y * 64;
    int colBase = blockIdx.x * 64;

    float acc[4][4] = {};

    for (int k0 = 0; k0 < K; k0 += 16) {
        // A tile load (transposed into As): thread loads 4 k-contiguous floats
        {
            int arow = tid >> 2;            // 0..63
            int ak   = (tid & 3) * 4;       // 0..12
            float4 av = *(const float4*)&A[(rowBase + arow) * K + k0 + ak];
            As[ak + 0][arow] = av.x;
            As[ak + 1][arow] = av.y;
            As[ak + 2][arow] = av.z;
            As[ak + 3][arow] = av.w;
        }
        // B tile load (direct)
        {
            int bk   = tid >> 4;            // 0..15
            int bcol = (tid & 15) * 4;      // 0..60
            *(float4*)&Bs[bk][bcol] =
                *(const float4*)&W[(k0 + bk) * N + colBase + bcol];
        }
        __syncthreads();

        #pragma unroll
        for (int kk = 0; kk < 16; kk++) {
            float4 a4 = *(const float4*)&As[kk][ty * 4];
            float4 b4 = *(const float4*)&Bs[kk][tx * 4];
            float a[4] = {a4.x, a4.y, a4.z, a4.w};
            float b[4] = {b4.x, b4.y, b4.z, b4.w};
            #pragma unroll
            for (int i = 0; i < 4; i++)
                #pragma unroll
                for (int j = 0; j < 4; j++)
                    acc[i][j] += a[i] * b[j];
        }
        __syncthreads();
    }

    // epilogue: bias + relu, float4 stores
    #pragma unroll
    for (int i = 0; i < 4; i++) {
        int r = rowBase + ty * 4 + i;
        float4 out;
        float* o = &out.x;
        #pragma unroll
        for (int j = 0; j < 4; j++) {
            float v = acc[i][j] + bias[colBase + tx * 4 + j];
            o[j] = v > 0.f ? v : 0.f;
        }
        *(float4*)&C[r * N + colBase + tx * 4] = out;
    }
}

// ---------------------------------------------------------------------------
// Flash attention: one CTA = (64 queries) x (one head) x (one batch).
// Online softmax over 32 key chunks of 64. Mask fills scaled score with 1e-9
// BEFORE softmax (exactly matching the reference).
// SMEM: QsT[d][q], KsT[d][k], Vs[k][d], PsT[k][q]  (all 64x64 fp32)
// ---------------------------------------------------------------------------
#define ATTN_SMEM ((4 * 64 * 64 + 3 * 64) * 4)

__global__ __launch_bounds__(256) void attention_kernel(
    const float* __restrict__ Q, const float* __restrict__ K,
    const float* __restrict__ V, const int* __restrict__ mask,
    float* __restrict__ O)
{
    extern __shared__ float sm[];
    float* QsT  = sm;                 // 4096
    float* KsT  = QsT + 4096;         // 4096
    float* Vs   = KsT + 4096;         // 4096
    float* PsT  = Vs  + 4096;         // 4096
    float* mrow = PsT + 4096;         // 64
    float* lrow = mrow + 64;          // 64
    float* arow = lrow + 64;          // 64
    __shared__ int mk[64];

    int tid = threadIdx.x;
    int tx = tid & 15;     // key / dim microtile col
    int ty = tid >> 4;     // query microtile row
    int qt = blockIdx.x;   // 0..31
    int h  = blockIdx.y;   // 0..15
    int b  = blockIdx.z;   // 0..1
    int qbase = qt * 64;
    const float scale = 0.125f;  // 64^-0.5

    // load Q tile transposed: QsT[d][q]
    {
        int qr = tid >> 2;               // 0..63
        int d0 = (tid & 3) * 16;         // 0,16,32,48
        const float* src = &Q[(size_t)(b * SEQ + qbase + qr) * DMODEL + h * DHEAD + d0];
        #pragma unroll
        for (int v = 0; v < 4; v++) {
            float4 q4 = *(const float4*)&src[v * 4];
            int d = d0 + v * 4;
            QsT[(d + 0) * 64 + qr] = q4.x;
            QsT[(d + 1) * 64 + qr] = q4.y;
            QsT[(d + 2) * 64 + qr] = q4.z;
            QsT[(d + 3) * 64 + qr] = q4.w;
        }
    }
    if (tid < 64) { mrow[tid] = -3.0e38f; lrow[tid] = 0.f; }

    float o[4][4] = {};

    for (int kc = 0; kc < SEQ / 64; kc++) {
        __syncthreads();   // protects KsT/Vs/PsT reuse; first iter: QsT/m/l ready

        // load K transposed + V direct + mask chunk
        {
            int kr = tid >> 2;
            int d0 = (tid & 3) * 16;
            size_t grow = (size_t)(b * SEQ + kc * 64 + kr) * DMODEL + h * DHEAD + d0;
            const float* ksrc = &K[grow];
            #pragma unroll
            for (int v = 0; v < 4; v++) {
                float4 k4 = *(const float4*)&ksrc[v * 4];
                int d = d0 + v * 4;
                KsT[(d + 0) * 64 + kr] = k4.x;
                KsT[(d + 1) * 64 + kr] = k4.y;
                KsT[(d + 2) * 64 + kr] = k4.z;
                KsT[(d + 3) * 64 + kr] = k4.w;
            }
            const float* vsrc = &V[grow];
            #pragma unroll
            for (int v = 0; v < 4; v++)
                *(float4*)&Vs[kr * 64 + d0 + v * 4] = *(const float4*)&vsrc[v * 4];
        }
        if (tid < 64) mk[tid] = mask[b * SEQ + kc * 64 + tid];
        __syncthreads();

        // S = Q K^T  (64x64), per-thread 4x4
        float s[4][4] = {};
        #pragma unroll 8
        for (int d = 0; d < 64; d++) {
            float4 a4 = *(const float4*)&QsT[d * 64 + ty * 4];
            float4 b4 = *(const float4*)&KsT[d * 64 + tx * 4];
            float a[4] = {a4.x, a4.y, a4.z, a4.w};
            float bb[4] = {b4.x, b4.y, b4.z, b4.w};
            #pragma unroll
            for (int i = 0; i < 4; i++)
                #pragma unroll
                for (int j = 0; j < 4; j++)
                    s[i][j] += a[i] * bb[j];
        }

        // write scaled + masked scores transposed: PsT[k][q]
        #pragma unroll
        for (int j = 0; j < 4; j++) {
            int kj = tx * 4 + j;
            bool msk = (mk[kj] != 0);
            #pragma unroll
            for (int i = 0; i < 4; i++) {
                float val = msk ? 1e-9f : s[i][j] * scale;
                PsT[kj * 64 + ty * 4 + i] = val;
            }
        }
        __syncthreads();

        // online softmax update, one thread per query row
        if (tid < 64) {
            int q = tid;
            float mold = mrow[q];
            float mc = mold;
            #pragma unroll 8
            for (int k2 = 0; k2 < 64; k2++)
                mc = fmaxf(mc, PsT[k2 * 64 + q]);
            float alpha = expf(mold - mc);
            float lsum = 0.f;
            #pragma unroll 4
            for (int k2 = 0; k2 < 64; k2++) {
                float p = expf(PsT[k2 * 64 + q] - mc);
                PsT[k2 * 64 + q] = p;
                lsum += p;
            }
            mrow[q] = mc;
            lrow[q] = lrow[q] * alpha + lsum;
            arow[q] = alpha;
        }
        __syncthreads();

        // rescale accumulator, then O += P @ V
        float al[4];
        #pragma unroll
        for (int i = 0; i < 4; i++) al[i] = arow[ty * 4 + i];
        #pragma unroll
        for (int i = 0; i < 4; i++)
            #pragma unroll
            for (int j = 0; j < 4; j++)
                o[i][j] *= al[i];

        #pragma unroll 8
        for (int k2 = 0; k2 < 64; k2++) {
            float4 a4 = *(const float4*)&PsT[k2 * 64 + ty * 4];
            float4 b4 = *(const float4*)&Vs[k2 * 64 + tx * 4];
            float a[4] = {a4.x, a4.y, a4.z, a4.w};
            float bb[4] = {b4.x, b4.y, b4.z, b4.w};
            #pragma unroll
            for (int i = 0; i < 4; i++)
                #pragma unroll
                for (int j = 0; j < 4; j++)
                    o[i][j] += a[i] * bb[j];
        }
    }

    // final normalize + store (lrow stable: last write synced before PV phase)
    #pragma unroll
    for (int i = 0; i < 4; i++) {
        int q = ty * 4 + i;
        float inv = 1.f / lrow[q];
        size_t grow = (size_t)(b * SEQ + qbase + q) * DMODEL + h * DHEAD + tx * 4;
        float4 out;
        out.x = o[i][0] * inv;
        out.y = o[i][1] * inv;
        out.z = o[i][2] * inv;
        out.w = o[i][3] * inv;
        *(float4*)&O[grow] = out;
    }
}

// ---------------------------------------------------------------------------
// launch
// ---------------------------------------------------------------------------
extern "C" void kernel_launch(void* const* d_in, const int* in_sizes, int n_in,
                              void* d_out, int out_size)
{
    const float* x    = (const float*)d_in[0];
    const int*   mask = (const int*)  d_in[1];
    const float* Wq   = (const float*)d_in[2];
    const float* bq   = (const float*)d_in[3];
    const float* Wk   = (const float*)d_in[4];
    const float* bk   = (const float*)d_in[5];
    const float* Wv   = (const float*)d_in[6];
    const float* bv   = (const float*)d_in[7];
    const float* Wo   = (const float*)d_in[8];
    const float* bo   = (const float*)d_in[9];
    float* out = (float*)d_out;

    float *Qp, *Kp, *Vp, *AOp;
    cudaGetSymbolAddress((void**)&Qp,  g_Q);
    cudaGetSymbolAddress((void**)&Kp,  g_K);
    cudaGetSymbolAddress((void**)&Vp,  g_V);
    cudaGetSymbolAddress((void**)&AOp, g_AO);

    cudaFuncSetAttribute(attention_kernel,
                         cudaFuncAttributeMaxDynamicSharedMemorySize, ATTN_SMEM);

    dim3 gg(1024 / 64, 4096 / 64);   // (N tiles, M tiles)
    gemm_bias_relu<<<gg, 256>>>(x, Wq, bq, Qp);
    gemm_bias_relu<<<gg, 256>>>(x, Wk, bk, Kp);
    gemm_bias_relu<<<gg, 256>>>(x, Wv, bv, Vp);

    attention_kernel<<<dim3(SEQ / 64, NHEAD, BATCH), 256, ATTN_SMEM>>>(
        Qp, Kp, Vp, mask, AOp);

    gemm_bias_relu<<<gg, 256>>>(AOp, Wo, bo, out);
}

// round 2
// speedup vs baseline: 1.4643x; 1.4643x over previous
#include <cuda_runtime.h>
#include <math.h>

// Problem constants
#define BATCH 2
#define SEQ   2048
#define DMODEL 1024
#define NHEAD 16
#define DHEAD 64
#define MROWS (BATCH * SEQ)   // 4096

// Scratch (allocation-free rule: __device__ globals)
__device__ float g_Q[MROWS * DMODEL];
__device__ float g_K[MROWS * DMODEL];
__device__ float g_V[MROWS * DMODEL];
__device__ float g_AO[MROWS * DMODEL];

// ---------------------------------------------------------------------------
// tf32 helpers
// ---------------------------------------------------------------------------
__device__ __forceinline__ unsigned f2tf32(float x) {
    unsigned r;
    asm("cvt.rna.tf32.f32 %0, %1;\n" : "=r"(r) : "f"(x));
    return r;
}

__device__ __forceinline__ void mma_tf32(
    float* d, const unsigned* a, const unsigned* b, const float* c)
{
    asm volatile(
        "mma.sync.aligned.m16n8k8.row.col.f32.tf32.tf32.f32 "
        "{%0,%1,%2,%3}, {%4,%5,%6,%7}, {%8,%9}, {%10,%11,%12,%13};\n"
        : "=f"(d[0]), "=f"(d[1]), "=f"(d[2]), "=f"(d[3])
        : "r"(a[0]), "r"(a[1]), "r"(a[2]), "r"(a[3]),
          "r"(b[0]), "r"(b[1]),
          "f"(c[0]), "f"(c[1]), "f"(c[2]), "f"(c[3]));
}

// ---------------------------------------------------------------------------
// tf32 tensor-core GEMM: C[4096,1024] = relu(A @ W + bias)
// BM=128, BN=128, BK=32. 256 threads = 8 warps, warp grid 2(m) x 4(n),
// each warp owns 64x32 via 4x4 grid of m16n8k8 mma tiles.
// SMEM holds tf32-converted bits (convert once at store time).
// A smem stride 36 words, B smem stride 136 words: both make the mma
// fragment LDS patterns bank-conflict-free and keep rows 16B-aligned.
// gridDim.z selects one of up to 3 (W, bias, C) problem instances.
// ---------------------------------------------------------------------------
__global__ __launch_bounds__(256) void gemm_tf32_bias_relu(
    const float* __restrict__ A,
    const float* __restrict__ W0, const float* __restrict__ b0, float* __restrict__ C0,
    const float* __restrict__ W1, const float* __restrict__ b1, float* __restrict__ C1,
    const float* __restrict__ W2, const float* __restrict__ b2, float* __restrict__ C2)
{
    const int N = 1024, K = 1024;
    __shared__ unsigned As[128][36];   // [m][k] tf32 bits
    __shared__ unsigned Bs[32][136];   // [k][n] tf32 bits

    const float* W; const float* bias; float* C;
    if (blockIdx.z == 0)      { W = W0; bias = b0; C = C0; }
    else if (blockIdx.z == 1) { W = W1; bias = b1; C = C1; }
    else                      { W = W2; bias = b2; C = C2; }

    int tid  = threadIdx.x;
    int lane = tid & 31;
    int warp = tid >> 5;
    int gid  = lane >> 2;     // groupID 0..7
    int tig  = lane & 3;      // thread in group 0..3

    int wm = warp & 1;        // 0..1 -> m offset
    int wn = warp >> 1;       // 0..3 -> n offset
    int m0w = wm * 64;
    int n0w = wn * 32;

    int rowBase = blockIdx.y * 128;
    int colBase = blockIdx.x * 128;

    float acc[4][4][4] = {};  // [mt][nt][reg]

    for (int k0 = 0; k0 < K; k0 += 32) {
        // --- load A tile 128x32: 4 float4 per thread ---
        #pragma unroll
        for (int v = 0; v < 4; v++) {
            int i = tid + v * 256;          // float4 index 0..1023
            int r = i >> 3;                 // 0..127
            int c = (i & 7) * 4;            // 0..28
            float4 a4 = *(const float4*)&A[(size_t)(rowBase + r) * K + k0 + c];
            uint4 u;
            u.x = f2tf32(a4.x); u.y = f2tf32(a4.y);
            u.z = f2tf32(a4.z); u.w = f2tf32(a4.w);
            *(uint4*)&As[r][c] = u;
        }
        // --- load B tile 32x128 ---
        #pragma unroll
        for (int v = 0; v < 4; v++) {
            int i = tid + v * 256;
            int r = i >> 5;                 // k row 0..31
            int c = (i & 31) * 4;           // 0..124
            float4 b4 = *(const float4*)&W[(size_t)(k0 + r) * N + colBase + c];
            uint4 u;
            u.x = f2tf32(b4.x); u.y = f2tf32(b4.y);
            u.z = f2tf32(b4.z); u.w = f2tf32(b4.w);
            *(uint4*)&Bs[r][c] = u;
        }
        __syncthreads();

        #pragma unroll
        for (int kk = 0; kk < 32; kk += 8) {
            unsigned af[4][4], bf[4][2];
            #pragma unroll
            for (int mt = 0; mt < 4; mt++) {
                int r = m0w + mt * 16 + gid;
                af[mt][0] = As[r    ][kk + tig];
                af[mt][1] = As[r + 8][kk + tig];
                af[mt][2] = As[r    ][kk + tig + 4];
                af[mt][3] = As[r + 8][kk + tig + 4];
            }
            #pragma unroll
            for (int nt = 0; nt < 4; nt++) {
                int c = n0w + nt * 8 + gid;
                bf[nt][0] = Bs[kk + tig    ][c];
                bf[nt][1] = Bs[kk + tig + 4][c];
            }
            #pragma unroll
            for (int mt = 0; mt < 4; mt++)
                #pragma unroll
                for (int nt = 0; nt < 4; nt++)
                    mma_tf32(acc[mt][nt], af[mt], bf[nt], acc[mt][nt]);
        }
        __syncthreads();
    }

    // epilogue: bias + relu, float2 stores (c0,c1) and (c2,c3)
    #pragma unroll
    for (int mt = 0; mt < 4; mt++) {
        #pragma unroll
        for (int nt = 0; nt < 4; nt++) {
            int col = colBase + n0w + nt * 8 + tig * 2;
            float bv0 = bias[col], bv1 = bias[col + 1];
            int r0 = rowBase + m0w + mt * 16 + gid;
            float2 o01, o23;
            o01.x = fmaxf(acc[mt][nt][0] + bv0, 0.f);
            o01.y = fmaxf(acc[mt][nt][1] + bv1, 0.f);
            o23.x = fmaxf(acc[mt][nt][2] + bv0, 0.f);
            o23.y = fmaxf(acc[mt][nt][3] + bv1, 0.f);
            *(float2*)&C[(size_t)r0 * N + col]       = o01;
            *(float2*)&C[(size_t)(r0 + 8) * N + col] = o23;
        }
    }
}

// ---------------------------------------------------------------------------
// Flash attention: one CTA = (64 queries) x (one head) x (one batch).
// Online softmax over 32 key chunks of 64. Mask fills scaled score with 1e-9
// BEFORE softmax (exactly matching the reference).
// SMEM: QsT[d][q], KsT[d][k], Vs[k][d], PsT[k][q]  (all 64x64 fp32)
// ---------------------------------------------------------------------------
#define ATTN_SMEM ((4 * 64 * 64 + 3 * 64) * 4)

__global__ __launch_bounds__(256) void attention_kernel(
    const float* __restrict__ Q, const float* __restrict__ K,
    const float* __restrict__ V, const int* __restrict__ mask,
    float* __restrict__ O)
{
    extern __shared__ float sm[];
    float* QsT  = sm;                 // 4096
    float* KsT  = QsT + 4096;         // 4096
    float* Vs   = KsT + 4096;         // 4096
    float* PsT  = Vs  + 4096;         // 4096
    float* mrow = PsT + 4096;         // 64
    float* lrow = mrow + 64;          // 64
    float* arow = lrow + 64;          // 64
    __shared__ int mk[64];

    int tid = threadIdx.x;
    int tx = tid & 15;     // key / dim microtile col
    int ty = tid >> 4;     // query microtile row
    int qt = blockIdx.x;   // 0..31
    int h  = blockIdx.y;   // 0..15
    int b  = blockIdx.z;   // 0..1
    int qbase = qt * 64;
    const float scale = 0.125f;  // 64^-0.5

    // load Q tile transposed: QsT[d][q]
    {
        int qr = tid >> 2;               // 0..63
        int d0 = (tid & 3) * 16;         // 0,16,32,48
        const float* src = &Q[(size_t)(b * SEQ + qbase + qr) * DMODEL + h * DHEAD + d0];
        #pragma unroll
        for (int v = 0; v < 4; v++) {
            float4 q4 = *(const float4*)&src[v * 4];
            int d = d0 + v * 4;
            QsT[(d + 0) * 64 + qr] = q4.x;
            QsT[(d + 1) * 64 + qr] = q4.y;
            QsT[(d + 2) * 64 + qr] = q4.z;
            QsT[(d + 3) * 64 + qr] = q4.w;
        }
    }
    if (tid < 64) { mrow[tid] = -3.0e38f; lrow[tid] = 0.f; }

    float o[4][4] = {};

    for (int kc = 0; kc < SEQ / 64; kc++) {
        __syncthreads();

        // load K transposed + V direct + mask chunk
        {
            int kr = tid >> 2;
            int d0 = (tid & 3) * 16;
            size_t grow = (size_t)(b * SEQ + kc * 64 + kr) * DMODEL + h * DHEAD + d0;
            const float* ksrc = &K[grow];
            #pragma unroll
            for (int v = 0; v < 4; v++) {
                float4 k4 = *(const float4*)&ksrc[v * 4];
                int d = d0 + v * 4;
                KsT[(d + 0) * 64 + kr] = k4.x;
                KsT[(d + 1) * 64 + kr] = k4.y;
                KsT[(d + 2) * 64 + kr] = k4.z;
                KsT[(d + 3) * 64 + kr] = k4.w;
            }
            const float* vsrc = &V[grow];
            #pragma unroll
            for (int v = 0; v < 4; v++)
                *(float4*)&Vs[kr * 64 + d0 + v * 4] = *(const float4*)&vsrc[v * 4];
        }
        if (tid < 64) mk[tid] = mask[b * SEQ + kc * 64 + tid];
        __syncthreads();

        // S = Q K^T  (64x64), per-thread 4x4
        float s[4][4] = {};
        #pragma unroll 8
        for (int d = 0; d < 64; d++) {
            float4 a4 = *(const float4*)&QsT[d * 64 + ty * 4];
            float4 b4 = *(const float4*)&KsT[d * 64 + tx * 4];
            float a[4] = {a4.x, a4.y, a4.z, a4.w};
            float bb[4] = {b4.x, b4.y, b4.z, b4.w};
            #pragma unroll
            for (int i = 0; i < 4; i++)
                #pragma unroll
                for (int j = 0; j < 4; j++)
                    s[i][j] += a[i] * bb[j];
        }

        // write scaled + masked scores transposed: PsT[k][q]
        #pragma unroll
        for (int j = 0; j < 4; j++) {
            int kj = tx * 4 + j;
            bool msk = (mk[kj] != 0);
            #pragma unroll
            for (int i = 0; i < 4; i++) {
                float val = msk ? 1e-9f : s[i][j] * scale;
                PsT[kj * 64 + ty * 4 + i] = val;
            }
        }
        __syncthreads();

        // online softmax update, one thread per query row
        if (tid < 64) {
            int q = tid;
            float mold = mrow[q];
            float mc = mold;
            #pragma unroll 8
            for (int k2 = 0; k2 < 64; k2++)
                mc = fmaxf(mc, PsT[k2 * 64 + q]);
            float alpha = expf(mold - mc);
            float lsum = 0.f;
            #pragma unroll 4
            for (int k2 = 0; k2 < 64; k2++) {
                float p = expf(PsT[k2 * 64 + q] - mc);
                PsT[k2 * 64 + q] = p;
                lsum += p;
            }
            mrow[q] = mc;
            lrow[q] = lrow[q] * alpha + lsum;
            arow[q] = alpha;
        }
        __syncthreads();

        // rescale accumulator, then O += P @ V
        float al[4];
        #pragma unroll
        for (int i = 0; i < 4; i++) al[i] = arow[ty * 4 + i];
        #pragma unroll
        for (int i = 0; i < 4; i++)
            #pragma unroll
            for (int j = 0; j < 4; j++)
                o[i][j] *= al[i];

        #pragma unroll 8
        for (int k2 = 0; k2 < 64; k2++) {
            float4 a4 = *(const float4*)&PsT[k2 * 64 + ty * 4];
            float4 b4 = *(const float4*)&Vs[k2 * 64 + tx * 4];
            float a[4] = {a4.x, a4.y, a4.z, a4.w};
            float bb[4] = {b4.x, b4.y, b4.z, b4.w};
            #pragma unroll
            for (int i = 0; i < 4; i++)
                #pragma unroll
                for (int j = 0; j < 4; j++)
                    o[i][j] += a[i] * bb[j];
        }
    }

    // final normalize + store
    #pragma unroll
    for (int i = 0; i < 4; i++) {
        int q = ty * 4 + i;
        float inv = 1.f / lrow[q];
        size_t grow = (size_t)(b * SEQ + qbase + q) * DMODEL + h * DHEAD + tx * 4;
        float4 out;
        out.x = o[i][0] * inv;
        out.y = o[i][1] * inv;
        out.z = o[i][2] * inv;
        out.w = o[i][3] * inv;
        *(float4*)&O[grow] = out;
    }
}

// ---------------------------------------------------------------------------
// launch
// ---------------------------------------------------------------------------
extern "C" void kernel_launch(void* const* d_in, const int* in_sizes, int n_in,
                              void* d_out, int out_size)
{
    const float* x    = (const float*)d_in[0];
    const int*   mask = (const int*)  d_in[1];
    const float* Wq   = (const float*)d_in[2];
    const float* bq   = (const float*)d_in[3];
    const float* Wk   = (const float*)d_in[4];
    const float* bk   = (const float*)d_in[5];
    const float* Wv   = (const float*)d_in[6];
    const float* bv   = (const float*)d_in[7];
    const float* Wo   = (const float*)d_in[8];
    const float* bo   = (const float*)d_in[9];
    float* out = (float*)d_out;

    float *Qp, *Kp, *Vp, *AOp;
    cudaGetSymbolAddress((void**)&Qp,  g_Q);
    cudaGetSymbolAddress((void**)&Kp,  g_K);
    cudaGetSymbolAddress((void**)&Vp,  g_V);
    cudaGetSymbolAddress((void**)&AOp, g_AO);

    cudaFuncSetAttribute(attention_kernel,
                         cudaFuncAttributeMaxDynamicSharedMemorySize, ATTN_SMEM);

    // fused Q/K/V projections: gridDim.z = 3
    dim3 gqkv(1024 / 128, 4096 / 128, 3);
    gemm_tf32_bias_relu<<<gqkv, 256>>>(x,
                                       Wq, bq, Qp,
                                       Wk, bk, Kp,
                                       Wv, bv, Vp);

    attention_kernel<<<dim3(SEQ / 64, NHEAD, BATCH), 256, ATTN_SMEM>>>(
        Qp, Kp, Vp, mask, AOp);

    // output projection
    dim3 go(1024 / 128, 4096 / 128, 1);
    gemm_tf32_bias_relu<<<go, 256>>>(AOp,
                                     Wo, bo, out,
                                     Wo, bo, out,
                                     Wo, bo, out);
}

// round 3
// speedup vs baseline: 2.7765x; 1.8961x over previous
#include <cuda_runtime.h>
#include <math.h>

// Problem constants
#define BATCH 2
#define SEQ   2048
#define DMODEL 1024
#define NHEAD 16
#define DHEAD 64
#define MROWS (BATCH * SEQ)   // 4096

// Scratch (allocation-free rule: __device__ globals)
__device__ float g_Q[MROWS * DMODEL];
__device__ float g_K[MROWS * DMODEL];
__device__ float g_V[MROWS * DMODEL];
__device__ float g_AO[MROWS * DMODEL];

// ---------------------------------------------------------------------------
// tf32 helpers
// ---------------------------------------------------------------------------
__device__ __forceinline__ unsigned f2tf32(float x) {
    unsigned r;
    asm("cvt.rna.tf32.f32 %0, %1;\n" : "=r"(r) : "f"(x));
    return r;
}

__device__ __forceinline__ void mma_tf32(
    float* d, const unsigned* a, const unsigned* b, const float* c)
{
    asm volatile(
        "mma.sync.aligned.m16n8k8.row.col.f32.tf32.tf32.f32 "
        "{%0,%1,%2,%3}, {%4,%5,%6,%7}, {%8,%9}, {%10,%11,%12,%13};\n"
        : "=f"(d[0]), "=f"(d[1]), "=f"(d[2]), "=f"(d[3])
        : "r"(a[0]), "r"(a[1]), "r"(a[2]), "r"(a[3]),
          "r"(b[0]), "r"(b[1]),
          "f"(c[0]), "f"(c[1]), "f"(c[2]), "f"(c[3]));
}

// ---------------------------------------------------------------------------
// tf32 tensor-core GEMM: C[4096,1024] = relu(A @ W + bias)   (unchanged R2)
// ---------------------------------------------------------------------------
__global__ __launch_bounds__(256) void gemm_tf32_bias_relu(
    const float* __restrict__ A,
    const float* __restrict__ W0, const float* __restrict__ b0, float* __restrict__ C0,
    const float* __restrict__ W1, const float* __restrict__ b1, float* __restrict__ C1,
    const float* __restrict__ W2, const float* __restrict__ b2, float* __restrict__ C2)
{
    const int N = 1024, K = 1024;
    __shared__ unsigned As[128][36];   // [m][k] tf32 bits
    __shared__ unsigned Bs[32][136];   // [k][n] tf32 bits

    const float* W; const float* bias; float* C;
    if (blockIdx.z == 0)      { W = W0; bias = b0; C = C0; }
    else if (blockIdx.z == 1) { W = W1; bias = b1; C = C1; }
    else                      { W = W2; bias = b2; C = C2; }

    int tid  = threadIdx.x;
    int lane = tid & 31;
    int warp = tid >> 5;
    int gid  = lane >> 2;
    int tig  = lane & 3;

    int wm = warp & 1;
    int wn = warp >> 1;
    int m0w = wm * 64;
    int n0w = wn * 32;

    int rowBase = blockIdx.y * 128;
    int colBase = blockIdx.x * 128;

    float acc[4][4][4] = {};

    for (int k0 = 0; k0 < K; k0 += 32) {
        #pragma unroll
        for (int v = 0; v < 4; v++) {
            int i = tid + v * 256;
            int r = i >> 3;
            int c = (i & 7) * 4;
            float4 a4 = *(const float4*)&A[(size_t)(rowBase + r) * K + k0 + c];
            uint4 u;
            u.x = f2tf32(a4.x); u.y = f2tf32(a4.y);
            u.z = f2tf32(a4.z); u.w = f2tf32(a4.w);
            *(uint4*)&As[r][c] = u;
        }
        #pragma unroll
        for (int v = 0; v < 4; v++) {
            int i = tid + v * 256;
            int r = i >> 5;
            int c = (i & 31) * 4;
            float4 b4 = *(const float4*)&W[(size_t)(k0 + r) * N + colBase + c];
            uint4 u;
            u.x = f2tf32(b4.x); u.y = f2tf32(b4.y);
            u.z = f2tf32(b4.z); u.w = f2tf32(b4.w);
            *(uint4*)&Bs[r][c] = u;
        }
        __syncthreads();

        #pragma unroll
        for (int kk = 0; kk < 32; kk += 8) {
            unsigned af[4][4], bf[4][2];
            #pragma unroll
            for (int mt = 0; mt < 4; mt++) {
                int r = m0w + mt * 16 + gid;
                af[mt][0] = As[r    ][kk + tig];
                af[mt][1] = As[r + 8][kk + tig];
                af[mt][2] = As[r    ][kk + tig + 4];
                af[mt][3] = As[r + 8][kk + tig + 4];
            }
            #pragma unroll
            for (int nt = 0; nt < 4; nt++) {
                int c = n0w + nt * 8 + gid;
                bf[nt][0] = Bs[kk + tig    ][c];
                bf[nt][1] = Bs[kk + tig + 4][c];
            }
            #pragma unroll
            for (int mt = 0; mt < 4; mt++)
                #pragma unroll
                for (int nt = 0; nt < 4; nt++)
                    mma_tf32(acc[mt][nt], af[mt], bf[nt], acc[mt][nt]);
        }
        __syncthreads();
    }

    #pragma unroll
    for (int mt = 0; mt < 4; mt++) {
        #pragma unroll
        for (int nt = 0; nt < 4; nt++) {
            int col = colBase + n0w + nt * 8 + tig * 2;
            float bv0 = bias[col], bv1 = bias[col + 1];
            int r0 = rowBase + m0w + mt * 16 + gid;
            float2 o01, o23;
            o01.x = fmaxf(acc[mt][nt][0] + bv0, 0.f);
            o01.y = fmaxf(acc[mt][nt][1] + bv1, 0.f);
            o23.x = fmaxf(acc[mt][nt][2] + bv0, 0.f);
            o23.y = fmaxf(acc[mt][nt][3] + bv1, 0.f);
            *(float2*)&C[(size_t)r0 * N + col]       = o01;
            *(float2*)&C[(size_t)(r0 + 8) * N + col] = o23;
        }
    }
}

// ---------------------------------------------------------------------------
// Tensor-core flash attention (tf32 mma).
// CTA = 64 queries x 1 head x 1 batch, 128 threads = 4 warps.
// Warp w owns query rows [16w, 16w+16). Q fragments live in registers.
// Per 64-key chunk: S = Q K^T via mma, register online softmax
// (2 rows/thread, quad shfl reductions), P -> SMEM (warp-private rows),
// O += P V via mma. Mask replaces scaled score with 1e-9 BEFORE softmax.
// SMEM strides: KsT/Vs 72 (=8 mod 32: B-frag LDS conflict-free),
// Ps 68 (=4 mod 32: A-frag LDS conflict-free).
// ---------------------------------------------------------------------------
#define KST_STRIDE 72
#define VS_STRIDE  72
#define PS_STRIDE  68
#define AT_SMEM_BYTES ((64*KST_STRIDE + 64*VS_STRIDE + 64*PS_STRIDE + 64) * 4)

__global__ __launch_bounds__(128) void attention_mma(
    const float* __restrict__ Q, const float* __restrict__ K,
    const float* __restrict__ V, const int* __restrict__ mask,
    float* __restrict__ O)
{
    extern __shared__ unsigned sm[];
    unsigned* KsT = sm;                          // [64][72]  (d, key)
    unsigned* Vs  = KsT + 64 * KST_STRIDE;       // [64][72]  (key, d)
    unsigned* Ps  = Vs  + 64 * VS_STRIDE;        // [64][68]  (q, key)
    int*      mk  = (int*)(Ps + 64 * PS_STRIDE); // [64]

    int tid  = threadIdx.x;
    int lane = tid & 31;
    int warp = tid >> 5;
    int gid  = lane >> 2;     // 0..7
    int tig  = lane & 3;      // 0..3
    int qt = blockIdx.x;      // 0..31
    int h  = blockIdx.y;      // 0..15
    int b  = blockIdx.z;      // 0..1
    int qbase = qt * 64;
    int m0 = warp * 16;
    const float scale = 0.125f;

    // --- load Q fragments into registers (held for whole kernel) ---
    unsigned qf[8][4];
    {
        const float* Qb = Q + (size_t)(b * SEQ + qbase + m0) * DMODEL + h * DHEAD;
        #pragma unroll
        for (int kt = 0; kt < 8; kt++) {
            int c = kt * 8 + tig;
            qf[kt][0] = f2tf32(Qb[(size_t)gid * DMODEL + c]);
            qf[kt][1] = f2tf32(Qb[(size_t)(gid + 8) * DMODEL + c]);
            qf[kt][2] = f2tf32(Qb[(size_t)gid * DMODEL + c + 4]);
            qf[kt][3] = f2tf32(Qb[(size_t)(gid + 8) * DMODEL + c + 4]);
        }
    }

    float oacc[8][4] = {};
    float mrow0 = -3.0e38f, mrow1 = -3.0e38f;
    float lrow0 = 0.f, lrow1 = 0.f;

    for (int kc = 0; kc < SEQ / 64; kc++) {
        __syncthreads();   // previous chunk's KsT/Vs reads complete

        // --- cooperative load of K (transposed) and V chunk ---
        {
            int kr = tid & 63;                 // key row in chunk
            int d0 = (tid >> 6) * 32;          // 0 or 32
            size_t grow = (size_t)(b * SEQ + kc * 64 + kr) * DMODEL + h * DHEAD + d0;
            const float* Kp = K + grow;
            const float* Vp = V + grow;
            #pragma unroll
            for (int v = 0; v < 8; v++) {
                float4 k4 = *(const float4*)&Kp[v * 4];
                int d = d0 + v * 4;
                KsT[(d + 0) * KST_STRIDE + kr] = f2tf32(k4.x);
                KsT[(d + 1) * KST_STRIDE + kr] = f2tf32(k4.y);
                KsT[(d + 2) * KST_STRIDE + kr] = f2tf32(k4.z);
                KsT[(d + 3) * KST_STRIDE + kr] = f2tf32(k4.w);
                float4 v4 = *(const float4*)&Vp[v * 4];
                uint4 u;
                u.x = f2tf32(v4.x); u.y = f2tf32(v4.y);
                u.z = f2tf32(v4.z); u.w = f2tf32(v4.w);
                *(uint4*)&Vs[kr * VS_STRIDE + d] = u;
            }
        }
        if (tid < 64) mk[tid] = mask[b * SEQ + kc * 64 + tid];
        __syncthreads();

        // --- S = Q K^T : 8 k-steps x 8 n-tiles ---
        float s[8][4] = {};
        #pragma unroll
        for (int kk = 0; kk < 8; kk++) {
            int kd = kk * 8;
            unsigned bf[8][2];
            #pragma unroll
            for (int nt = 0; nt < 8; nt++) {
                int c = nt * 8 + gid;
                bf[nt][0] = KsT[(kd + tig    ) * KST_STRIDE + c];
                bf[nt][1] = KsT[(kd + tig + 4) * KST_STRIDE + c];
            }
            #pragma unroll
            for (int nt = 0; nt < 8; nt++)
                mma_tf32(s[nt], qf[kk], bf[nt], s[nt]);
        }

        // --- mask + scale, register online softmax ---
        float mnew0 = mrow0, mnew1 = mrow1;
        #pragma unroll
        for (int nt = 0; nt < 8; nt++) {
            int c = nt * 8 + 2 * tig;
            bool k0m = (mk[c] != 0), k1m = (mk[c + 1] != 0);
            s[nt][0] = k0m ? 1e-9f : s[nt][0] * scale;
            s[nt][1] = k1m ? 1e-9f : s[nt][1] * scale;
            s[nt][2] = k0m ? 1e-9f : s[nt][2] * scale;
            s[nt][3] = k1m ? 1e-9f : s[nt][3] * scale;
            mnew0 = fmaxf(mnew0, fmaxf(s[nt][0], s[nt][1]));
            mnew1 = fmaxf(mnew1, fmaxf(s[nt][2], s[nt][3]));
        }
        mnew0 = fmaxf(mnew0, __shfl_xor_sync(0xffffffff, mnew0, 1));
        mnew0 = fmaxf(mnew0, __shfl_xor_sync(0xffffffff, mnew0, 2));
        mnew1 = fmaxf(mnew1, __shfl_xor_sync(0xffffffff, mnew1, 1));
        mnew1 = fmaxf(mnew1, __shfl_xor_sync(0xffffffff, mnew1, 2));

        float alpha0 = __expf(mrow0 - mnew0);
        float alpha1 = __expf(mrow1 - mnew1);
        mrow0 = mnew0; mrow1 = mnew1;

        float sum0 = 0.f, sum1 = 0.f;
        int prow0 = (m0 + gid) * PS_STRIDE;
        int prow1 = (m0 + gid + 8) * PS_STRIDE;
        #pragma unroll
        for (int nt = 0; nt < 8; nt++) {
            int c = nt * 8 + 2 * tig;
            float p0 = __expf(s[nt][0] - mnew0);
            float p1 = __expf(s[nt][1] - mnew0);
            float p2 = __expf(s[nt][2] - mnew1);
            float p3 = __expf(s[nt][3] - mnew1);
            sum0 += p0 + p1;
            sum1 += p2 + p3;
            uint2 w0; w0.x = f2tf32(p0); w0.y = f2tf32(p1);
            uint2 w1; w1.x = f2tf32(p2); w1.y = f2tf32(p3);
            *(uint2*)&Ps[prow0 + c] = w0;
            *(uint2*)&Ps[prow1 + c] = w1;
        }
        sum0 += __shfl_xor_sync(0xffffffff, sum0, 1);
        sum0 += __shfl_xor_sync(0xffffffff, sum0, 2);
        sum1 += __shfl_xor_sync(0xffffffff, sum1, 1);
        sum1 += __shfl_xor_sync(0xffffffff, sum1, 2);
        lrow0 = lrow0 * alpha0 + sum0;
        lrow1 = lrow1 * alpha1 + sum1;

        // rescale O accumulator
        #pragma unroll
        for (int dt = 0; dt < 8; dt++) {
            oacc[dt][0] *= alpha0; oacc[dt][1] *= alpha0;
            oacc[dt][2] *= alpha1; oacc[dt][3] *= alpha1;
        }

        __syncwarp();   // Ps rows are warp-private

        // --- O += P V : 8 k-steps (key) x 8 n-tiles (d) ---
        #pragma unroll
        for (int kk = 0; kk < 8; kk++) {
            int kd = kk * 8;
            unsigned af[4];
            af[0] = Ps[prow0 + kd + tig];
            af[1] = Ps[prow1 + kd + tig];
            af[2] = Ps[prow0 + kd + tig + 4];
            af[3] = Ps[prow1 + kd + tig + 4];
            unsigned bf[8][2];
            #pragma unroll
            for (int dt = 0; dt < 8; dt++) {
                int c = dt * 8 + gid;
                bf[dt][0] = Vs[(kd + tig    ) * VS_STRIDE + c];
                bf[dt][1] = Vs[(kd + tig + 4) * VS_STRIDE + c];
            }
            #pragma unroll
            for (int dt = 0; dt < 8; dt++)
                mma_tf32(oacc[dt], af, bf[dt], oacc[dt]);
        }
        __syncwarp();   // Ps reads done before next chunk's writes
    }

    // --- epilogue: normalize + store ---
    float inv0 = 1.f / lrow0;
    float inv1 = 1.f / lrow1;
    size_t r0 = (size_t)(b * SEQ + qbase + m0 + gid) * DMODEL + h * DHEAD;
    size_t r1 = (size_t)(b * SEQ + qbase + m0 + gid + 8) * DMODEL + h * DHEAD;
    #pragma unroll
    for (int dt = 0; dt < 8; dt++) {
        int c = dt * 8 + 2 * tig;
        float2 o0; o0.x = oacc[dt][0] * inv0; o0.y = oacc[dt][1] * inv0;
        float2 o1; o1.x = oacc[dt][2] * inv1; o1.y = oacc[dt][3] * inv1;
        *(float2*)&O[r0 + c] = o0;
        *(float2*)&O[r1 + c] = o1;
    }
}

// ---------------------------------------------------------------------------
// launch
// ---------------------------------------------------------------------------
extern "C" void kernel_launch(void* const* d_in, const int* in_sizes, int n_in,
                              void* d_out, int out_size)
{
    const float* x    = (const float*)d_in[0];
    const int*   mask = (const int*)  d_in[1];
    const float* Wq   = (const float*)d_in[2];
    const float* bq   = (const float*)d_in[3];
    const float* Wk   = (const float*)d_in[4];
    const float* bk   = (const float*)d_in[5];
    const float* Wv   = (const float*)d_in[6];
    const float* bv   = (const float*)d_in[7];
    const float* Wo   = (const float*)d_in[8];
    const float* bo   = (const float*)d_in[9];
    float* out = (float*)d_out;

    float *Qp, *Kp, *Vp, *AOp;
    cudaGetSymbolAddress((void**)&Qp,  g_Q);
    cudaGetSymbolAddress((void**)&Kp,  g_K);
    cudaGetSymbolAddress((void**)&Vp,  g_V);
    cudaGetSymbolAddress((void**)&AOp, g_AO);

    cudaFuncSetAttribute(attention_mma,
                         cudaFuncAttributeMaxDynamicSharedMemorySize, AT_SMEM_BYTES);

    dim3 gqkv(1024 / 128, 4096 / 128, 3);
    gemm_tf32_bias_relu<<<gqkv, 256>>>(x,
                                       Wq, bq, Qp,
                                       Wk, bk, Kp,
                                       Wv, bv, Vp);

    attention_mma<<<dim3(SEQ / 64, NHEAD, BATCH), 128, AT_SMEM_BYTES>>>(
        Qp, Kp, Vp, mask, AOp);

    dim3 go(1024 / 128, 4096 / 128, 1);
    gemm_tf32_bias_relu<<<go, 256>>>(AOp,
                                     Wo, bo, out,
                                     Wo, bo, out,
                                     Wo, bo, out);
}

// round 5
// speedup vs baseline: 4.0597x; 1.4622x over previous
#include <cuda_runtime.h>
#include <math.h>

// Problem constants
#define BATCH 2
#define SEQ   2048
#define DMODEL 1024
#define NHEAD 16
#define DHEAD 64
#define MROWS (BATCH * SEQ)   // 4096

// Scratch (allocation-free rule: __device__ globals)
__device__ float g_Q[MROWS * DMODEL];     // holds tf32-RNA bits
__device__ float g_K[MROWS * DMODEL];     // holds tf32-RNA bits
__device__ float g_V[MROWS * DMODEL];     // holds tf32-RNA bits
__device__ float g_AO[MROWS * DMODEL];    // holds tf32-RNA bits
__device__ unsigned g_xc [MROWS * DMODEL];      // x  -> tf32 bits
__device__ unsigned g_Wqc[DMODEL * DMODEL];
__device__ unsigned g_Wkc[DMODEL * DMODEL];
__device__ unsigned g_Wvc[DMODEL * DMODEL];
__device__ unsigned g_Woc[DMODEL * DMODEL];

// ---------------------------------------------------------------------------
// helpers
// ---------------------------------------------------------------------------
__device__ __forceinline__ unsigned f2tf32(float x) {
    unsigned r;
    asm("cvt.rna.tf32.f32 %0, %1;\n" : "=r"(r) : "f"(x));
    return r;
}

__device__ __forceinline__ void mma_tf32(
    float* d, const unsigned* a, const unsigned* b, const float* c)
{
    asm volatile(
        "mma.sync.aligned.m16n8k8.row.col.f32.tf32.tf32.f32 "
        "{%0,%1,%2,%3}, {%4,%5,%6,%7}, {%8,%9}, {%10,%11,%12,%13};\n"
        : "=f"(d[0]), "=f"(d[1]), "=f"(d[2]), "=f"(d[3])
        : "r"(a[0]), "r"(a[1]), "r"(a[2]), "r"(a[3]),
          "r"(b[0]), "r"(b[1]),
          "f"(c[0]), "f"(c[1]), "f"(c[2]), "f"(c[3]));
}

__device__ __forceinline__ void cp_async16(void* smem_ptr, const void* gmem_ptr) {
    unsigned saddr = (unsigned)__cvta_generic_to_shared(smem_ptr);
    asm volatile("cp.async.cg.shared.global [%0], [%1], 16;\n"
                 :: "r"(saddr), "l"(gmem_ptr));
}
__device__ __forceinline__ void cp_commit() {
    asm volatile("cp.async.commit_group;\n");
}
template<int N> __device__ __forceinline__ void cp_wait() {
    asm volatile("cp.async.wait_group %0;\n" :: "n"(N));
}

// ---------------------------------------------------------------------------
// elementwise fp32 -> tf32(RNA) bits
// ---------------------------------------------------------------------------
__global__ __launch_bounds__(256) void cvt_tf32(
    const float* __restrict__ in, unsigned* __restrict__ out, int n4)
{
    int i = blockIdx.x * 256 + threadIdx.x;
    if (i < n4) {
        float4 v = *(const float4*)&in[i * 4];
        uint4 u;
        u.x = f2tf32(v.x); u.y = f2tf32(v.y);
        u.z = f2tf32(v.z); u.w = f2tf32(v.w);
        *(uint4*)&out[i * 4] = u;
    }
}

// ---------------------------------------------------------------------------
// tf32 tensor-core GEMM, cp.async double-buffered. Inputs are PRE-ROUNDED
// tf32 bits -> no cvt anywhere in the kernel.
// C = relu(A @ W + bias); epilogue stores tf32-RNA bits if roundOut,
// else plain fp32. BM=128 BN=128 BK=32, 256 threads, 8 warps 2(m)x4(n).
// As stride 36 (4 mod 32), Bs stride 136 (8 mod 32): frag LDS conflict-free.
// ---------------------------------------------------------------------------
#define GEMM_SMEM_WORDS (2*128*36 + 2*32*136)
#define GEMM_SMEM_BYTES (GEMM_SMEM_WORDS * 4)

__global__ __launch_bounds__(256) void gemm_tf32_bias_relu(
    const unsigned* __restrict__ A,
    const unsigned* __restrict__ W0, const float* __restrict__ b0, float* __restrict__ C0,
    const unsigned* __restrict__ W1, const float* __restrict__ b1, float* __restrict__ C1,
    const unsigned* __restrict__ W2, const float* __restrict__ b2, float* __restrict__ C2,
    int roundOut)
{
    const int N = 1024, K = 1024;
    extern __shared__ unsigned smg[];
    unsigned* As = smg;                 // [2][128][36]
    unsigned* Bs = smg + 2 * 128 * 36;  // [2][32][136]

    const unsigned* W; const float* bias; float* C;
    if (blockIdx.z == 0)      { W = W0; bias = b0; C = C0; }
    else if (blockIdx.z == 1) { W = W1; bias = b1; C = C1; }
    else                      { W = W2; bias = b2; C = C2; }

    int tid  = threadIdx.x;
    int lane = tid & 31;
    int warp = tid >> 5;
    int gid  = lane >> 2;
    int tig  = lane & 3;

    int m0w = (warp & 1) * 64;
    int n0w = (warp >> 1) * 32;

    int rowBase = blockIdx.y * 128;
    int colBase = blockIdx.x * 128;

    int ar = tid >> 3;
    int ac = (tid & 7) * 4;
    int br = tid >> 5;
    int bc = (tid & 31) * 4;

    float acc[4][4][4] = {};

    {
        #pragma unroll
        for (int v = 0; v < 4; v++) {
            int r = ar + v * 32, c = ac;
            cp_async16(&As[(size_t)r * 36 + c], &A[(size_t)(rowBase + r) * K + c]);
        }
        #pragma unroll
        for (int v = 0; v < 4; v++) {
            int r = br + v * 8, c = bc;
            cp_async16(&Bs[(size_t)r * 136 + c], &W[(size_t)r * N + colBase + c]);
        }
        cp_commit();
    }

    #pragma unroll 1
    for (int it = 0; it < 32; it++) {
        int buf = it & 1;
        if (it + 1 < 32) {
            int k0n = (it + 1) * 32;
            unsigned* An = As + (buf ^ 1) * 128 * 36;
            unsigned* Bn = Bs + (buf ^ 1) * 32 * 136;
            #pragma unroll
            for (int v = 0; v < 4; v++) {
                int r = ar + v * 32, c = ac;
                cp_async16(&An[(size_t)r * 36 + c],
                           &A[(size_t)(rowBase + r) * K + k0n + c]);
            }
            #pragma unroll
            for (int v = 0; v < 4; v++) {
                int r = br + v * 8, c = bc;
                cp_async16(&Bn[(size_t)r * 136 + c],
                           &W[(size_t)(k0n + r) * N + colBase + c]);
            }
            cp_commit();
            cp_wait<1>();
        } else {
            cp_wait<0>();
        }
        __syncthreads();

        unsigned* Ab = As + buf * 128 * 36;
        unsigned* Bb = Bs + buf * 32 * 136;

        #pragma unroll
        for (int kk = 0; kk < 32; kk += 8) {
            unsigned af[4][4], bf[4][2];
            #pragma unroll
            for (int mt = 0; mt < 4; mt++) {
                int r = m0w + mt * 16 + gid;
                af[mt][0] = Ab[(size_t)r * 36 + kk + tig];
                af[mt][1] = Ab[(size_t)(r + 8) * 36 + kk + tig];
                af[mt][2] = Ab[(size_t)r * 36 + kk + tig + 4];
                af[mt][3] = Ab[(size_t)(r + 8) * 36 + kk + tig + 4];
            }
            #pragma unroll
            for (int nt = 0; nt < 4; nt++) {
                int c = n0w + nt * 8 + gid;
                bf[nt][0] = Bb[(size_t)(kk + tig) * 136 + c];
                bf[nt][1] = Bb[(size_t)(kk + tig + 4) * 136 + c];
            }
            #pragma unroll
            for (int mt = 0; mt < 4; mt++)
                #pragma unroll
                for (int nt = 0; nt < 4; nt++)
                    mma_tf32(acc[mt][nt], af[mt], bf[nt], acc[mt][nt]);
        }
        __syncthreads();
    }

    #pragma unroll
    for (int mt = 0; mt < 4; mt++) {
        #pragma unroll
        for (int nt = 0; nt < 4; nt++) {
            int col = colBase + n0w + nt * 8 + tig * 2;
            float bv0 = bias[col], bv1 = bias[col + 1];
            int r0 = rowBase + m0w + mt * 16 + gid;
            float v00 = fmaxf(acc[mt][nt][0] + bv0, 0.f);
            float v01 = fmaxf(acc[mt][nt][1] + bv1, 0.f);
            float v10 = fmaxf(acc[mt][nt][2] + bv0, 0.f);
            float v11 = fmaxf(acc[mt][nt][3] + bv1, 0.f);
            if (roundOut) {
                uint2 u0, u1;
                u0.x = f2tf32(v00); u0.y = f2tf32(v01);
                u1.x = f2tf32(v10); u1.y = f2tf32(v11);
                *(uint2*)&C[(size_t)r0 * N + col]       = u0;
                *(uint2*)&C[(size_t)(r0 + 8) * N + col] = u1;
            } else {
                float2 o0, o1;
                o0.x = v00; o0.y = v01;
                o1.x = v10; o1.y = v11;
                *(float2*)&C[(size_t)r0 * N + col]       = o0;
                *(float2*)&C[(size_t)(r0 + 8) * N + col] = o1;
            }
        }
    }
}

// ---------------------------------------------------------------------------
// Tensor-core flash attention, cp.async double-buffered K/V/mask.
// Q/K/V arrive as pre-rounded tf32 bits (QKV-gemm epilogue). Only P needs
// in-kernel cvt.rna. AO stored as tf32 bits for the out-projection.
// CTA = 64 queries x 1 head x 1 batch, 128 threads = 4 warps.
// K natural [key][d] stride 68; V [key][d] stride 72; Ps stride 68.
// Register online softmax; mask fill 1e-9 BEFORE softmax.
// ---------------------------------------------------------------------------
#define KS_STRIDE 68
#define VS_STRIDE 72
#define PS_STRIDE 68
#define AT_KS_WORDS (2 * 64 * KS_STRIDE)
#define AT_VS_WORDS (2 * 64 * VS_STRIDE)
#define AT_PS_WORDS (64 * PS_STRIDE)
#define AT_SMEM_BYTES ((AT_KS_WORDS + AT_VS_WORDS + AT_PS_WORDS + 2 * 64) * 4)

__global__ __launch_bounds__(128) void attention_mma(
    const float* __restrict__ Q, const float* __restrict__ K,
    const float* __restrict__ V, const int* __restrict__ mask,
    float* __restrict__ O)
{
    extern __shared__ unsigned sm[];
    unsigned* Ks = sm;                       // [2][64][68]
    unsigned* Vs = Ks + AT_KS_WORDS;         // [2][64][72]
    unsigned* Ps = Vs + AT_VS_WORDS;         // [64][68]
    int*      mk = (int*)(Ps + AT_PS_WORDS); // [2][64]

    int tid  = threadIdx.x;
    int lane = tid & 31;
    int warp = tid >> 5;
    int gid  = lane >> 2;
    int tig  = lane & 3;
    int qt = blockIdx.x;
    int h  = blockIdx.y;
    int b  = blockIdx.z;
    int qbase = qt * 64;
    int m0 = warp * 16;
    const float scale = 0.125f;

    const size_t headOff = (size_t)h * DHEAD;
    const size_t bRow = (size_t)b * SEQ;

    int lrow = tid >> 4;
    int lcol = (tid & 15) * 4;

    // Q fragments: already tf32-rounded bits in memory
    unsigned qf[8][4];
    {
        const float* Qb = Q + (bRow + qbase + m0) * DMODEL + headOff;
        #pragma unroll
        for (int kt = 0; kt < 8; kt++) {
            int c = kt * 8 + tig;
            qf[kt][0] = __float_as_uint(Qb[(size_t)gid * DMODEL + c]);
            qf[kt][1] = __float_as_uint(Qb[(size_t)(gid + 8) * DMODEL + c]);
            qf[kt][2] = __float_as_uint(Qb[(size_t)gid * DMODEL + c + 4]);
            qf[kt][3] = __float_as_uint(Qb[(size_t)(gid + 8) * DMODEL + c + 4]);
        }
    }

    {
        #pragma unroll
        for (int v = 0; v < 8; v++) {
            int row = lrow + v * 8;
            size_t g = (bRow + row) * DMODEL + headOff + lcol;
            cp_async16(&Ks[(size_t)row * KS_STRIDE + lcol], &K[g]);
            cp_async16(&Vs[(size_t)row * VS_STRIDE + lcol], &V[g]);
        }
        if (tid < 16) cp_async16(&mk[tid * 4], &mask[bRow + tid * 4]);
        cp_commit();
    }

    float oacc[8][4] = {};
    float mrow0 = -3.0e38f, mrow1 = -3.0e38f;
    float lrow0 = 0.f, lrow1 = 0.f;

    #pragma unroll 1
    for (int kc = 0; kc < SEQ / 64; kc++) {
        int buf = kc & 1;
        if (kc + 1 < SEQ / 64) {
            int nb = buf ^ 1;
            unsigned* Kn = Ks + nb * 64 * KS_STRIDE;
            unsigned* Vn = Vs + nb * 64 * VS_STRIDE;
            #pragma unroll
            for (int v = 0; v < 8; v++) {
                int row = lrow + v * 8;
                size_t g = (bRow + (kc + 1) * 64 + row) * DMODEL + headOff + lcol;
                cp_async16(&Kn[(size_t)row * KS_STRIDE + lcol], &K[g]);
                cp_async16(&Vn[(size_t)row * VS_STRIDE + lcol], &V[g]);
            }
            if (tid < 16)
                cp_async16(&mk[nb * 64 + tid * 4],
                           &mask[bRow + (kc + 1) * 64 + tid * 4]);
            cp_commit();
            cp_wait<1>();
        } else {
            cp_wait<0>();
        }
        __syncthreads();

        unsigned* Kb = Ks + buf * 64 * KS_STRIDE;
        unsigned* Vb = Vs + buf * 64 * VS_STRIDE;
        int* mkb = mk + buf * 64;

        // S = Q K^T
        float s[8][4] = {};
        #pragma unroll
        for (int kk = 0; kk < 8; kk++) {
            int kd = kk * 8;
            unsigned bf[8][2];
            #pragma unroll
            for (int nt = 0; nt < 8; nt++) {
                int key = nt * 8 + gid;
                bf[nt][0] = Kb[(size_t)key * KS_STRIDE + kd + tig];
                bf[nt][1] = Kb[(size_t)key * KS_STRIDE + kd + tig + 4];
            }
            #pragma unroll
            for (int nt = 0; nt < 8; nt++)
                mma_tf32(s[nt], qf[kk], bf[nt], s[nt]);
        }

        // mask + scale + register online softmax
        float mnew0 = mrow0, mnew1 = mrow1;
        #pragma unroll
        for (int nt = 0; nt < 8; nt++) {
            int c = nt * 8 + 2 * tig;
            bool k0m = (mkb[c] != 0), k1m = (mkb[c + 1] != 0);
            s[nt][0] = k0m ? 1e-9f : s[nt][0] * scale;
            s[nt][1] = k1m ? 1e-9f : s[nt][1] * scale;
            s[nt][2] = k0m ? 1e-9f : s[nt][2] * scale;
            s[nt][3] = k1m ? 1e-9f : s[nt][3] * scale;
            mnew0 = fmaxf(mnew0, fmaxf(s[nt][0], s[nt][1]));
            mnew1 = fmaxf(mnew1, fmaxf(s[nt][2], s[nt][3]));
        }
        mnew0 = fmaxf(mnew0, __shfl_xor_sync(0xffffffff, mnew0, 1));
        mnew0 = fmaxf(mnew0, __shfl_xor_sync(0xffffffff, mnew0, 2));
        mnew1 = fmaxf(mnew1, __shfl_xor_sync(0xffffffff, mnew1, 1));
        mnew1 = fmaxf(mnew1, __shfl_xor_sync(0xffffffff, mnew1, 2));

        float alpha0 = __expf(mrow0 - mnew0);
        float alpha1 = __expf(mrow1 - mnew1);
        mrow0 = mnew0; mrow1 = mnew1;

        float sum0 = 0.f, sum1 = 0.f;
        int prow0 = (m0 + gid) * PS_STRIDE;
        int prow1 = (m0 + gid + 8) * PS_STRIDE;
        #pragma unroll
        for (int nt = 0; nt < 8; nt++) {
            int c = nt * 8 + 2 * tig;
            float p0 = __expf(s[nt][0] - mnew0);
            float p1 = __expf(s[nt][1] - mnew0);
            float p2 = __expf(s[nt][2] - mnew1);
            float p3 = __expf(s[nt][3] - mnew1);
            sum0 += p0 + p1;
            sum1 += p2 + p3;
            uint2 w0; w0.x = f2tf32(p0); w0.y = f2tf32(p1);
            uint2 w1; w1.x = f2tf32(p2); w1.y = f2tf32(p3);
            *(uint2*)&Ps[prow0 + c] = w0;
            *(uint2*)&Ps[prow1 + c] = w1;
        }
        sum0 += __shfl_xor_sync(0xffffffff, sum0, 1);
        sum0 += __shfl_xor_sync(0xffffffff, sum0, 2);
        sum1 += __shfl_xor_sync(0xffffffff, sum1, 1);
        sum1 += __shfl_xor_sync(0xffffffff, sum1, 2);
        lrow0 = lrow0 * alpha0 + sum0;
        lrow1 = lrow1 * alpha1 + sum1;

        #pragma unroll
        for (int dt = 0; dt < 8; dt++) {
            oacc[dt][0] *= alpha0; oacc[dt][1] *= alpha0;
            oacc[dt][2] *= alpha1; oacc[dt][3] *= alpha1;
        }

        __syncwarp();   // Ps rows are warp-private

        // O += P V
        #pragma unroll
        for (int kk = 0; kk < 8; kk++) {
            int kd = kk * 8;
            unsigned af[4];
            af[0] = Ps[prow0 + kd + tig];
            af[1] = Ps[prow1 + kd + tig];
            af[2] = Ps[prow0 + kd + tig + 4];
            af[3] = Ps[prow1 + kd + tig + 4];
            unsigned bf[8][2];
            #pragma unroll
            for (int dt = 0; dt < 8; dt++) {
                int c = dt * 8 + gid;
                bf[dt][0] = Vb[(size_t)(kd + tig) * VS_STRIDE + c];
                bf[dt][1] = Vb[(size_t)(kd + tig + 4) * VS_STRIDE + c];
            }
            #pragma unroll
            for (int dt = 0; dt < 8; dt++)
                mma_tf32(oacc[dt], af, bf[dt], oacc[dt]);
        }
        __syncthreads();   // buf reused by next iter's cp.async
    }

    // epilogue: normalize + store as tf32-RNA bits (consumed only by mma)
    float inv0 = 1.f / lrow0;
    float inv1 = 1.f / lrow1;
    size_t r0 = (bRow + qbase + m0 + gid) * DMODEL + headOff;
    size_t r1 = (bRow + qbase + m0 + gid + 8) * DMODEL + headOff;
    #pragma unroll
    for (int dt = 0; dt < 8; dt++) {
        int c = dt * 8 + 2 * tig;
        uint2 o0, o1;
        o0.x = f2tf32(oacc[dt][0] * inv0); o0.y = f2tf32(oacc[dt][1] * inv0);
        o1.x = f2tf32(oacc[dt][2] * inv1); o1.y = f2tf32(oacc[dt][3] * inv1);
        *(uint2*)&O[r0 + c] = o0;
        *(uint2*)&O[r1 + c] = o1;
    }
}

// ---------------------------------------------------------------------------
// launch
// ---------------------------------------------------------------------------
extern "C" void kernel_launch(void* const* d_in, const int* in_sizes, int n_in,
                              void* d_out, int out_size)
{
    const float* x    = (const float*)d_in[0];
    const int*   mask = (const int*)  d_in[1];
    const float* Wq   = (const float*)d_in[2];
    const float* bq   = (const float*)d_in[3];
    const float* Wk   = (const float*)d_in[4];
    const float* bk   = (const float*)d_in[5];
    const float* Wv   = (const float*)d_in[6];
    const float* bv   = (const float*)d_in[7];
    const float* Wo   = (const float*)d_in[8];
    const float* bo   = (const float*)d_in[9];
    float* out = (float*)d_out;

    float *Qp, *Kp, *Vp, *AOp;
    unsigned *xc, *Wqc, *Wkc, *Wvc, *Woc;
    cudaGetSymbolAddress((void**)&Qp,  g_Q);
    cudaGetSymbolAddress((void**)&Kp,  g_K);
    cudaGetSymbolAddress((void**)&Vp,  g_V);
    cudaGetSymbolAddress((void**)&AOp, g_AO);
    cudaGetSymbolAddress((void**)&xc,  g_xc);
    cudaGetSymbolAddress((void**)&Wqc, g_Wqc);
    cudaGetSymbolAddress((void**)&Wkc, g_Wkc);
    cudaGetSymbolAddress((void**)&Wvc, g_Wvc);
    cudaGetSymbolAddress((void**)&Woc, g_Woc);

    cudaFuncSetAttribute(gemm_tf32_bias_relu,
                         cudaFuncAttributeMaxDynamicSharedMemorySize, GEMM_SMEM_BYTES);
    cudaFuncSetAttribute(attention_mma,
                         cudaFuncAttributeMaxDynamicSharedMemorySize, AT_SMEM_BYTES);

    // pre-round inputs to tf32 (RNA), once
    int nx4 = MROWS * DMODEL / 4;      // 1,048,576
    int nw4 = DMODEL * DMODEL / 4;     //   262,144
    cvt_tf32<<<(nx4 + 255) / 256, 256>>>(x,  xc,  nx4);
    cvt_tf32<<<(nw4 + 255) / 256, 256>>>(Wq, Wqc, nw4);
    cvt_tf32<<<(nw4 + 255) / 256, 256>>>(Wk, Wkc, nw4);
    cvt_tf32<<<(nw4 + 255) / 256, 256>>>(Wv, Wvc, nw4);
    cvt_tf32<<<(nw4 + 255) / 256, 256>>>(Wo, Woc, nw4);

    // fused Q/K/V projections (outputs rounded to tf32 bits)
    dim3 gqkv(1024 / 128, 4096 / 128, 3);
    gemm_tf32_bias_relu<<<gqkv, 256, GEMM_SMEM_BYTES>>>(xc,
                                       Wqc, bq, Qp,
                                       Wkc, bk, Kp,
                                       Wvc, bv, Vp, 1);

    attention_mma<<<dim3(SEQ / 64, NHEAD, BATCH), 128, AT_SMEM_BYTES>>>(
        Qp, Kp, Vp, mask, AOp);

    // output projection (exact fp32 store)
    dim3 go(1024 / 128, 4096 / 128, 1);
    gemm_tf32_bias_relu<<<go, 256, GEMM_SMEM_BYTES>>>((const unsigned*)AOp,
                                     Woc, bo, out,
                                     Woc, bo, out,
                                     Woc, bo, out, 0);
}

// round 6
// speedup vs baseline: 4.3391x; 1.0688x over previous
#include <cuda_runtime.h>
#include <math.h>

// Problem constants
#define BATCH 2
#define SEQ   2048
#define DMODEL 1024
#define NHEAD 16
#define DHEAD 64
#define MROWS (BATCH * SEQ)   // 4096

// Scratch (allocation-free rule: __device__ globals)
__device__ float g_Q[MROWS * DMODEL];     // tf32-RNA bits
__device__ float g_K[MROWS * DMODEL];     // tf32-RNA bits
__device__ float g_V[MROWS * DMODEL];     // tf32-RNA bits
__device__ float g_AO[MROWS * DMODEL];    // tf32-RNA bits
__device__ unsigned g_xc [MROWS * DMODEL];
__device__ unsigned g_Wqc[DMODEL * DMODEL];
__device__ unsigned g_Wkc[DMODEL * DMODEL];
__device__ unsigned g_Wvc[DMODEL * DMODEL];
__device__ unsigned g_Woc[DMODEL * DMODEL];

// ---------------------------------------------------------------------------
// helpers
// ---------------------------------------------------------------------------
__device__ __forceinline__ unsigned f2tf32(float x) {
    unsigned r;
    asm("cvt.rna.tf32.f32 %0, %1;\n" : "=r"(r) : "f"(x));
    return r;
}

__device__ __forceinline__ void mma_tf32(
    float* d, const unsigned* a, const unsigned* b, const float* c)
{
    asm volatile(
        "mma.sync.aligned.m16n8k8.row.col.f32.tf32.tf32.f32 "
        "{%0,%1,%2,%3}, {%4,%5,%6,%7}, {%8,%9}, {%10,%11,%12,%13};\n"
        : "=f"(d[0]), "=f"(d[1]), "=f"(d[2]), "=f"(d[3])
        : "r"(a[0]), "r"(a[1]), "r"(a[2]), "r"(a[3]),
          "r"(b[0]), "r"(b[1]),
          "f"(c[0]), "f"(c[1]), "f"(c[2]), "f"(c[3]));
}

__device__ __forceinline__ void cp_async16(void* smem_ptr, const void* gmem_ptr) {
    unsigned saddr = (unsigned)__cvta_generic_to_shared(smem_ptr);
    asm volatile("cp.async.cg.shared.global [%0], [%1], 16;\n"
                 :: "r"(saddr), "l"(gmem_ptr));
}
__device__ __forceinline__ void cp_commit() {
    asm volatile("cp.async.commit_group;\n");
}
template<int N> __device__ __forceinline__ void cp_wait() {
    asm volatile("cp.async.wait_group %0;\n" :: "n"(N));
}

// ---------------------------------------------------------------------------
// fused elementwise fp32 -> tf32(RNA) bits for x + 4 weight matrices
// ---------------------------------------------------------------------------
#define NX4 (MROWS * DMODEL / 4)     // 1,048,576
#define NW4 (DMODEL * DMODEL / 4)    //   262,144 = 2^18

__global__ __launch_bounds__(256) void cvt_all(
    const float* __restrict__ x,
    const float* __restrict__ wq, const float* __restrict__ wk,
    const float* __restrict__ wv, const float* __restrict__ wo,
    unsigned* __restrict__ xc,
    unsigned* __restrict__ wqc, unsigned* __restrict__ wkc,
    unsigned* __restrict__ wvc, unsigned* __restrict__ woc)
{
    int i = blockIdx.x * 256 + threadIdx.x;
    const float* in; unsigned* out; int off;
    if (i < NX4) { in = x; out = xc; off = i; }
    else {
        int r = i - NX4;
        int j = r >> 18;
        off = r & (NW4 - 1);
        if (j == 0)      { in = wq; out = wqc; }
        else if (j == 1) { in = wk; out = wkc; }
        else if (j == 2) { in = wv; out = wvc; }
        else             { in = wo; out = woc; }
    }
    float4 v = *(const float4*)&in[(size_t)off * 4];
    uint4 u;
    u.x = f2tf32(v.x); u.y = f2tf32(v.y);
    u.z = f2tf32(v.z); u.w = f2tf32(v.w);
    *(uint4*)&out[(size_t)off * 4] = u;
}

// ---------------------------------------------------------------------------
// tf32 tensor-core GEMM, cp.async double-buffered (pre-rounded tf32 inputs).
// C = relu(A @ W + bias); epilogue stores tf32 bits if roundOut else fp32.
// BM=128 BN=128 BK=32, 256 threads, 8 warps 2(m)x4(n).
// ---------------------------------------------------------------------------
#define GEMM_SMEM_WORDS (2*128*36 + 2*32*136)
#define GEMM_SMEM_BYTES (GEMM_SMEM_WORDS * 4)

__global__ __launch_bounds__(256) void gemm_tf32_bias_relu(
    const unsigned* __restrict__ A,
    const unsigned* __restrict__ W0, const float* __restrict__ b0, float* __restrict__ C0,
    const unsigned* __restrict__ W1, const float* __restrict__ b1, float* __restrict__ C1,
    const unsigned* __restrict__ W2, const float* __restrict__ b2, float* __restrict__ C2,
    int roundOut)
{
    const int N = 1024, K = 1024;
    extern __shared__ unsigned smg[];
    unsigned* As = smg;                 // [2][128][36]
    unsigned* Bs = smg + 2 * 128 * 36;  // [2][32][136]

    const unsigned* W; const float* bias; float* C;
    if (blockIdx.z == 0)      { W = W0; bias = b0; C = C0; }
    else if (blockIdx.z == 1) { W = W1; bias = b1; C = C1; }
    else                      { W = W2; bias = b2; C = C2; }

    int tid  = threadIdx.x;
    int lane = tid & 31;
    int warp = tid >> 5;
    int gid  = lane >> 2;
    int tig  = lane & 3;

    int m0w = (warp & 1) * 64;
    int n0w = (warp >> 1) * 32;

    int rowBase = blockIdx.y * 128;
    int colBase = blockIdx.x * 128;

    int ar = tid >> 3;
    int ac = (tid & 7) * 4;
    int br = tid >> 5;
    int bc = (tid & 31) * 4;

    float acc[4][4][4] = {};

    {
        #pragma unroll
        for (int v = 0; v < 4; v++) {
            int r = ar + v * 32, c = ac;
            cp_async16(&As[(size_t)r * 36 + c], &A[(size_t)(rowBase + r) * K + c]);
        }
        #pragma unroll
        for (int v = 0; v < 4; v++) {
            int r = br + v * 8, c = bc;
            cp_async16(&Bs[(size_t)r * 136 + c], &W[(size_t)r * N + colBase + c]);
        }
        cp_commit();
    }

    #pragma unroll 1
    for (int it = 0; it < 32; it++) {
        int buf = it & 1;
        if (it + 1 < 32) {
            int k0n = (it + 1) * 32;
            unsigned* An = As + (buf ^ 1) * 128 * 36;
            unsigned* Bn = Bs + (buf ^ 1) * 32 * 136;
            #pragma unroll
            for (int v = 0; v < 4; v++) {
                int r = ar + v * 32, c = ac;
                cp_async16(&An[(size_t)r * 36 + c],
                           &A[(size_t)(rowBase + r) * K + k0n + c]);
            }
            #pragma unroll
            for (int v = 0; v < 4; v++) {
                int r = br + v * 8, c = bc;
                cp_async16(&Bn[(size_t)r * 136 + c],
                           &W[(size_t)(k0n + r) * N + colBase + c]);
            }
            cp_commit();
            cp_wait<1>();
        } else {
            cp_wait<0>();
        }
        __syncthreads();

        unsigned* Ab = As + buf * 128 * 36;
        unsigned* Bb = Bs + buf * 32 * 136;

        #pragma unroll
        for (int kk = 0; kk < 32; kk += 8) {
            unsigned af[4][4], bf[4][2];
            #pragma unroll
            for (int mt = 0; mt < 4; mt++) {
                int r = m0w + mt * 16 + gid;
                af[mt][0] = Ab[(size_t)r * 36 + kk + tig];
                af[mt][1] = Ab[(size_t)(r + 8) * 36 + kk + tig];
                af[mt][2] = Ab[(size_t)r * 36 + kk + tig + 4];
                af[mt][3] = Ab[(size_t)(r + 8) * 36 + kk + tig + 4];
            }
            #pragma unroll
            for (int nt = 0; nt < 4; nt++) {
                int c = n0w + nt * 8 + gid;
                bf[nt][0] = Bb[(size_t)(kk + tig) * 136 + c];
                bf[nt][1] = Bb[(size_t)(kk + tig + 4) * 136 + c];
            }
            #pragma unroll
            for (int mt = 0; mt < 4; mt++)
                #pragma unroll
                for (int nt = 0; nt < 4; nt++)
                    mma_tf32(acc[mt][nt], af[mt], bf[nt], acc[mt][nt]);
        }
        __syncthreads();
    }

    #pragma unroll
    for (int mt = 0; mt < 4; mt++) {
        #pragma unroll
        for (int nt = 0; nt < 4; nt++) {
            int col = colBase + n0w + nt * 8 + tig * 2;
            float bv0 = bias[col], bv1 = bias[col + 1];
            int r0 = rowBase + m0w + mt * 16 + gid;
            float v00 = fmaxf(acc[mt][nt][0] + bv0, 0.f);
            float v01 = fmaxf(acc[mt][nt][1] + bv1, 0.f);
            float v10 = fmaxf(acc[mt][nt][2] + bv0, 0.f);
            float v11 = fmaxf(acc[mt][nt][3] + bv1, 0.f);
            if (roundOut) {
                uint2 u0, u1;
                u0.x = f2tf32(v00); u0.y = f2tf32(v01);
                u1.x = f2tf32(v10); u1.y = f2tf32(v11);
                *(uint2*)&C[(size_t)r0 * N + col]       = u0;
                *(uint2*)&C[(size_t)(r0 + 8) * N + col] = u1;
            } else {
                float2 o0, o1;
                o0.x = v00; o0.y = v01;
                o1.x = v10; o1.y = v11;
                *(float2*)&C[(size_t)r0 * N + col]       = o0;
                *(float2*)&C[(size_t)(r0 + 8) * N + col] = o1;
            }
        }
    }
}

// ---------------------------------------------------------------------------
// Tensor-core flash attention v2.
// CTA = 128 queries x 1 head x 1 batch, 128 threads = 4 warps.
// Each warp owns 32 query rows (2 m16 tiles) -> K/V B-fragments amortized
// over 2x queries. K natural [key][d] stride 68; V [key][d] stride 72;
// Ps [128 q][68]. cp.async double-buffered K/V/mask. Register online
// softmax (4 rows/thread). Mask fill 1e-9 BEFORE softmax.
// ---------------------------------------------------------------------------
#define KS_STRIDE 68
#define VS_STRIDE 72
#define PS_STRIDE 68
#define AT_KS_WORDS (2 * 64 * KS_STRIDE)
#define AT_VS_WORDS (2 * 64 * VS_STRIDE)
#define AT_PS_WORDS (128 * PS_STRIDE)
#define AT_SMEM_BYTES ((AT_KS_WORDS + AT_VS_WORDS + AT_PS_WORDS + 2 * 64) * 4)

__global__ __launch_bounds__(128) void attention_mma(
    const float* __restrict__ Q, const float* __restrict__ K,
    const float* __restrict__ V, const int* __restrict__ mask,
    float* __restrict__ O)
{
    extern __shared__ unsigned sm[];
    unsigned* Ks = sm;                       // [2][64][68]
    unsigned* Vs = Ks + AT_KS_WORDS;         // [2][64][72]
    unsigned* Ps = Vs + AT_VS_WORDS;         // [128][68]
    int*      mk = (int*)(Ps + AT_PS_WORDS); // [2][64]

    int tid  = threadIdx.x;
    int lane = tid & 31;
    int warp = tid >> 5;
    int gid  = lane >> 2;     // 0..7
    int tig  = lane & 3;      // 0..3
    int qt = blockIdx.x;      // 0..15
    int h  = blockIdx.y;
    int b  = blockIdx.z;
    int qbase = qt * 128;
    int m0 = warp * 32;       // 32 query rows per warp
    const float scale = 0.125f;

    const size_t headOff = (size_t)h * DHEAD;
    const size_t bRow = (size_t)b * SEQ;

    int ldr  = tid >> 4;            // 0..7
    int ldc  = (tid & 15) * 4;

    // --- Q fragments for both m-tiles (tf32 bits already) ---
    unsigned qf[2][8][4];
    {
        const float* Qb = Q + (bRow + qbase + m0) * DMODEL + headOff;
        #pragma unroll
        for (int mt = 0; mt < 2; mt++) {
            #pragma unroll
            for (int kt = 0; kt < 8; kt++) {
                int c = kt * 8 + tig;
                size_t r0 = (size_t)(mt * 16 + gid) * DMODEL;
                size_t r1 = (size_t)(mt * 16 + gid + 8) * DMODEL;
                qf[mt][kt][0] = __float_as_uint(Qb[r0 + c]);
                qf[mt][kt][1] = __float_as_uint(Qb[r1 + c]);
                qf[mt][kt][2] = __float_as_uint(Qb[r0 + c + 4]);
                qf[mt][kt][3] = __float_as_uint(Qb[r1 + c + 4]);
            }
        }
    }

    // --- issue chunk 0 ---
    {
        #pragma unroll
        for (int v = 0; v < 8; v++) {
            int row = ldr + v * 8;
            size_t g = (bRow + row) * DMODEL + headOff + ldc;
            cp_async16(&Ks[(size_t)row * KS_STRIDE + ldc], &K[g]);
            cp_async16(&Vs[(size_t)row * VS_STRIDE + ldc], &V[g]);
        }
        if (tid < 16) cp_async16(&mk[tid * 4], &mask[bRow + tid * 4]);
        cp_commit();
    }

    float oacc[2][8][4] = {};
    float mS[2][2] = {{-3.0e38f, -3.0e38f}, {-3.0e38f, -3.0e38f}};
    float lS[2][2] = {{0.f, 0.f}, {0.f, 0.f}};

    #pragma unroll 1
    for (int kc = 0; kc < SEQ / 64; kc++) {
        int buf = kc & 1;
        if (kc + 1 < SEQ / 64) {
            int nb = buf ^ 1;
            unsigned* Kn = Ks + nb * 64 * KS_STRIDE;
            unsigned* Vn = Vs + nb * 64 * VS_STRIDE;
            #pragma unroll
            for (int v = 0; v < 8; v++) {
                int row = ldr + v * 8;
                size_t g = (bRow + (kc + 1) * 64 + row) * DMODEL + headOff + ldc;
                cp_async16(&Kn[(size_t)row * KS_STRIDE + ldc], &K[g]);
                cp_async16(&Vn[(size_t)row * VS_STRIDE + ldc], &V[g]);
            }
            if (tid < 16)
                cp_async16(&mk[nb * 64 + tid * 4],
                           &mask[bRow + (kc + 1) * 64 + tid * 4]);
            cp_commit();
            cp_wait<1>();
        } else {
            cp_wait<0>();
        }
        __syncthreads();

        unsigned* Kb = Ks + buf * 64 * KS_STRIDE;
        unsigned* Vb = Vs + buf * 64 * VS_STRIDE;
        int* mkb = mk + buf * 64;

        // --- S = Q K^T : B-frags shared across both m-tiles ---
        float s[2][8][4] = {};
        #pragma unroll
        for (int kk = 0; kk < 8; kk++) {
            int kd = kk * 8;
            unsigned bf[8][2];
            #pragma unroll
            for (int nt = 0; nt < 8; nt++) {
                int key = nt * 8 + gid;
                bf[nt][0] = Kb[(size_t)key * KS_STRIDE + kd + tig];
                bf[nt][1] = Kb[(size_t)key * KS_STRIDE + kd + tig + 4];
            }
            #pragma unroll
            for (int nt = 0; nt < 8; nt++) {
                mma_tf32(s[0][nt], qf[0][kk], bf[nt], s[0][nt]);
                mma_tf32(s[1][nt], qf[1][kk], bf[nt], s[1][nt]);
            }
        }

        // --- mask + scale + online softmax (4 rows/thread) ---
        float mnew[2][2] = {{mS[0][0], mS[0][1]}, {mS[1][0], mS[1][1]}};
        #pragma unroll
        for (int nt = 0; nt < 8; nt++) {
            int c = nt * 8 + 2 * tig;
            bool k0m = (mkb[c] != 0), k1m = (mkb[c + 1] != 0);
            #pragma unroll
            for (int mt = 0; mt < 2; mt++) {
                s[mt][nt][0] = k0m ? 1e-9f : s[mt][nt][0] * scale;
                s[mt][nt][1] = k1m ? 1e-9f : s[mt][nt][1] * scale;
                s[mt][nt][2] = k0m ? 1e-9f : s[mt][nt][2] * scale;
                s[mt][nt][3] = k1m ? 1e-9f : s[mt][nt][3] * scale;
                mnew[mt][0] = fmaxf(mnew[mt][0], fmaxf(s[mt][nt][0], s[mt][nt][1]));
                mnew[mt][1] = fmaxf(mnew[mt][1], fmaxf(s[mt][nt][2], s[mt][nt][3]));
            }
        }
        #pragma unroll
        for (int mt = 0; mt < 2; mt++) {
            #pragma unroll
            for (int hh = 0; hh < 2; hh++) {
                mnew[mt][hh] = fmaxf(mnew[mt][hh],
                                     __shfl_xor_sync(0xffffffff, mnew[mt][hh], 1));
                mnew[mt][hh] = fmaxf(mnew[mt][hh],
                                     __shfl_xor_sync(0xffffffff, mnew[mt][hh], 2));
            }
        }

        float alpha[2][2];
        #pragma unroll
        for (int mt = 0; mt < 2; mt++)
            #pragma unroll
            for (int hh = 0; hh < 2; hh++) {
                alpha[mt][hh] = __expf(mS[mt][hh] - mnew[mt][hh]);
                mS[mt][hh] = mnew[mt][hh];
            }

        #pragma unroll
        for (int mt = 0; mt < 2; mt++) {
            float sum0 = 0.f, sum1 = 0.f;
            int prow0 = (m0 + mt * 16 + gid) * PS_STRIDE;
            int prow1 = (m0 + mt * 16 + gid + 8) * PS_STRIDE;
            #pragma unroll
            for (int nt = 0; nt < 8; nt++) {
                int c = nt * 8 + 2 * tig;
                float p0 = __expf(s[mt][nt][0] - mnew[mt][0]);
                float p1 = __expf(s[mt][nt][1] - mnew[mt][0]);
                float p2 = __expf(s[mt][nt][2] - mnew[mt][1]);
                float p3 = __expf(s[mt][nt][3] - mnew[mt][1]);
                sum0 += p0 + p1;
                sum1 += p2 + p3;
                uint2 w0; w0.x = f2tf32(p0); w0.y = f2tf32(p1);
                uint2 w1; w1.x = f2tf32(p2); w1.y = f2tf32(p3);
                *(uint2*)&Ps[prow0 + c] = w0;
                *(uint2*)&Ps[prow1 + c] = w1;
            }
            sum0 += __shfl_xor_sync(0xffffffff, sum0, 1);
            sum0 += __shfl_xor_sync(0xffffffff, sum0, 2);
            sum1 += __shfl_xor_sync(0xffffffff, sum1, 1);
            sum1 += __shfl_xor_sync(0xffffffff, sum1, 2);
            lS[mt][0] = lS[mt][0] * alpha[mt][0] + sum0;
            lS[mt][1] = lS[mt][1] * alpha[mt][1] + sum1;
            #pragma unroll
            for (int dt = 0; dt < 8; dt++) {
                oacc[mt][dt][0] *= alpha[mt][0];
                oacc[mt][dt][1] *= alpha[mt][0];
                oacc[mt][dt][2] *= alpha[mt][1];
                oacc[mt][dt][3] *= alpha[mt][1];
            }
        }

        __syncwarp();   // Ps rows are warp-private

        // --- O += P V : V-frags shared across both m-tiles ---
        #pragma unroll
        for (int kk = 0; kk < 8; kk++) {
            int kd = kk * 8;
            unsigned af0[4], af1[4];
            {
                int p00 = (m0 + gid) * PS_STRIDE;
                int p01 = (m0 + gid + 8) * PS_STRIDE;
                int p10 = (m0 + 16 + gid) * PS_STRIDE;
                int p11 = (m0 + 16 + gid + 8) * PS_STRIDE;
                af0[0] = Ps[p00 + kd + tig];
                af0[1] = Ps[p01 + kd + tig];
                af0[2] = Ps[p00 + kd + tig + 4];
                af0[3] = Ps[p01 + kd + tig + 4];
                af1[0] = Ps[p10 + kd + tig];
                af1[1] = Ps[p11 + kd + tig];
                af1[2] = Ps[p10 + kd + tig + 4];
                af1[3] = Ps[p11 + kd + tig + 4];
            }
            unsigned bf[8][2];
            #pragma unroll
            for (int dt = 0; dt < 8; dt++) {
                int c = dt * 8 + gid;
                bf[dt][0] = Vb[(size_t)(kd + tig) * VS_STRIDE + c];
                bf[dt][1] = Vb[(size_t)(kd + tig + 4) * VS_STRIDE + c];
            }
            #pragma unroll
            for (int dt = 0; dt < 8; dt++) {
                mma_tf32(oacc[0][dt], af0, bf[dt], oacc[0][dt]);
                mma_tf32(oacc[1][dt], af1, bf[dt], oacc[1][dt]);
            }
        }
        __syncthreads();   // K/V buffer reused by next iter's cp.async
    }

    // --- epilogue: normalize + store tf32 bits (consumed only by mma) ---
    #pragma unroll
    for (int mt = 0; mt < 2; mt++) {
        float inv0 = 1.f / lS[mt][0];
        float inv1 = 1.f / lS[mt][1];
        size_t r0 = (bRow + qbase + m0 + mt * 16 + gid) * DMODEL + headOff;
        size_t r1 = (bRow + qbase + m0 + mt * 16 + gid + 8) * DMODEL + headOff;
        #pragma unroll
        for (int dt = 0; dt < 8; dt++) {
            int c = dt * 8 + 2 * tig;
            uint2 o0, o1;
            o0.x = f2tf32(oacc[mt][dt][0] * inv0);
            o0.y = f2tf32(oacc[mt][dt][1] * inv0);
            o1.x = f2tf32(oacc[mt][dt][2] * inv1);
            o1.y = f2tf32(oacc[mt][dt][3] * inv1);
            *(uint2*)&O[r0 + c] = o0;
            *(uint2*)&O[r1 + c] = o1;
        }
    }
}

// ---------------------------------------------------------------------------
// launch
// ---------------------------------------------------------------------------
extern "C" void kernel_launch(void* const* d_in, const int* in_sizes, int n_in,
                              void* d_out, int out_size)
{
    const float* x    = (const float*)d_in[0];
    const int*   mask = (const int*)  d_in[1];
    const float* Wq   = (const float*)d_in[2];
    const float* bq   = (const float*)d_in[3];
    const float* Wk   = (const float*)d_in[4];
    const float* bk   = (const float*)d_in[5];
    const float* Wv   = (const float*)d_in[6];
    const float* bv   = (const float*)d_in[7];
    const float* Wo   = (const float*)d_in[8];
    const float* bo   = (const float*)d_in[9];
    float* out = (float*)d_out;

    float *Qp, *Kp, *Vp, *AOp;
    unsigned *xc, *Wqc, *Wkc, *Wvc, *Woc;
    cudaGetSymbolAddress((void**)&Qp,  g_Q);
    cudaGetSymbolAddress((void**)&Kp,  g_K);
    cudaGetSymbolAddress((void**)&Vp,  g_V);
    cudaGetSymbolAddress((void**)&AOp, g_AO);
    cudaGetSymbolAddress((void**)&xc,  g_xc);
    cudaGetSymbolAddress((void**)&Wqc, g_Wqc);
    cudaGetSymbolAddress((void**)&Wkc, g_Wkc);
    cudaGetSymbolAddress((void**)&Wvc, g_Wvc);
    cudaGetSymbolAddress((void**)&Woc, g_Woc);

    cudaFuncSetAttribute(gemm_tf32_bias_relu,
                         cudaFuncAttributeMaxDynamicSharedMemorySize, GEMM_SMEM_BYTES);
    cudaFuncSetAttribute(attention_mma,
                         cudaFuncAttributeMaxDynamicSharedMemorySize, AT_SMEM_BYTES);

    // fused pre-round of x and all weights (one launch)
    int total4 = NX4 + 4 * NW4;
    cvt_all<<<(total4 + 255) / 256, 256>>>(x, Wq, Wk, Wv, Wo,
                                           xc, Wqc, Wkc, Wvc, Woc);

    // fused Q/K/V projections (outputs rounded to tf32 bits)
    dim3 gqkv(1024 / 128, 4096 / 128, 3);
    gemm_tf32_bias_relu<<<gqkv, 256, GEMM_SMEM_BYTES>>>(xc,
                                       Wqc, bq, Qp,
                                       Wkc, bk, Kp,
                                       Wvc, bv, Vp, 1);

    attention_mma<<<dim3(SEQ / 128, NHEAD, BATCH), 128, AT_SMEM_BYTES>>>(
        Qp, Kp, Vp, mask, AOp);

    // output projection (exact fp32 store)
    dim3 go(1024 / 128, 4096 / 128, 1);
    gemm_tf32_bias_relu<<<go, 256, GEMM_SMEM_BYTES>>>((const unsigned*)AOp,
                                     Woc, bo, out,
                                     Woc, bo, out,
                                     Woc, bo, out, 0);
}

// round 7
// speedup vs baseline: 6.9015x; 1.5905x over previous
#include <cuda_runtime.h>
#include <cuda_fp16.h>
#include <math.h>

// Problem constants
#define BATCH 2
#define SEQ   2048
#define DMODEL 1024
#define NHEAD 16
#define DHEAD 64
#define MROWS (BATCH * SEQ)   // 4096

// Scratch (allocation-free rule: __device__ globals)
__device__ __half g_xh [MROWS * DMODEL];         // x  fp16 [row][k]
__device__ __half g_Wqh[DMODEL * DMODEL];        // Wq^T fp16 [n][k]
__device__ __half g_Wkh[DMODEL * DMODEL];
__device__ __half g_Wvh[DMODEL * DMODEL];
__device__ __half g_Woh[DMODEL * DMODEL];
__device__ __half g_Q  [MROWS * DMODEL];         // fp16 [row][h*64+d]
__device__ __half g_K  [MROWS * DMODEL];         // fp16 [row][h*64+d]
__device__ __half g_V  [MROWS * DMODEL];         // fp16 TRANSPOSED [b][h][d][s]
__device__ __half g_AO [MROWS * DMODEL];         // fp16 [row][h*64+d]

// ---------------------------------------------------------------------------
// helpers
// ---------------------------------------------------------------------------
__device__ __forceinline__ unsigned pack_half2(float a, float b) {
    __half2 h = __floats2half2_rn(a, b);
    return *(unsigned*)&h;
}

__device__ __forceinline__ void mma_fp16(
    float* d, const unsigned* a, const unsigned* b, const float* c)
{
    asm volatile(
        "mma.sync.aligned.m16n8k16.row.col.f32.f16.f16.f32 "
        "{%0,%1,%2,%3}, {%4,%5,%6,%7}, {%8,%9}, {%10,%11,%12,%13};\n"
        : "=f"(d[0]), "=f"(d[1]), "=f"(d[2]), "=f"(d[3])
        : "r"(a[0]), "r"(a[1]), "r"(a[2]), "r"(a[3]),
          "r"(b[0]), "r"(b[1]),
          "f"(c[0]), "f"(c[1]), "f"(c[2]), "f"(c[3]));
}

__device__ __forceinline__ void cp_async16(void* smem_ptr, const void* gmem_ptr) {
    unsigned saddr = (unsigned)__cvta_generic_to_shared(smem_ptr);
    asm volatile("cp.async.cg.shared.global [%0], [%1], 16;\n"
                 :: "r"(saddr), "l"(gmem_ptr));
}
__device__ __forceinline__ void cp_commit() {
    asm volatile("cp.async.commit_group;\n");
}
template<int N> __device__ __forceinline__ void cp_wait() {
    asm volatile("cp.async.wait_group %0;\n" :: "n"(N));
}

// ---------------------------------------------------------------------------
// cvt x -> fp16 (identity layout). One thread: 8 floats -> 8 halves.
// ---------------------------------------------------------------------------
__global__ __launch_bounds__(256) void cvt_x_fp16(
    const float* __restrict__ x, __half* __restrict__ xh)
{
    int i = blockIdx.x * 256 + threadIdx.x;     // 0 .. MROWS*DMODEL/8-1
    float4 v0 = *(const float4*)&x[(size_t)i * 8];
    float4 v1 = *(const float4*)&x[(size_t)i * 8 + 4];
    uint4 u;
    u.x = pack_half2(v0.x, v0.y);
    u.y = pack_half2(v0.z, v0.w);
    u.z = pack_half2(v1.x, v1.y);
    u.w = pack_half2(v1.z, v1.w);
    *(uint4*)&xh[(size_t)i * 8] = u;
}

// ---------------------------------------------------------------------------
// transpose + cvt weights: W[k][n] fp32 -> WT[n][k] fp16.  32x32 tiles,
// block (32,8). gridDim.z selects the matrix.
// ---------------------------------------------------------------------------
__global__ __launch_bounds__(256) void cvt_w_t(
    const float* __restrict__ wq, const float* __restrict__ wk,
    const float* __restrict__ wv, const float* __restrict__ wo)
{
    __shared__ __half tile[32][33];
    const float* W; __half* WT;
    if (blockIdx.z == 0)      { W = wq; WT = g_Wqh; }
    else if (blockIdx.z == 1) { W = wk; WT = g_Wkh; }
    else if (blockIdx.z == 2) { W = wv; WT = g_Wvh; }
    else                      { W = wo; WT = g_Woh; }

    int tx = threadIdx.x, ty = threadIdx.y;
    int bx = blockIdx.x * 32, by = blockIdx.y * 32;
    #pragma unroll
    for (int j = 0; j < 4; j++) {
        int r = by + ty + j * 8;
        tile[ty + j * 8][tx] = __float2half(W[(size_t)r * DMODEL + bx + tx]);
    }
    __syncthreads();
    #pragma unroll
    for (int j = 0; j < 4; j++) {
        int r = bx + ty + j * 8;
        WT[(size_t)r * DMODEL + by + tx] = tile[tx][ty + j * 8];
    }
}

// ---------------------------------------------------------------------------
// fp16 tensor-core GEMM, cp.async double-buffered.
// C = relu(A @ W^T' + bias) where A[m][k], WT[n][k] both fp16 k-contiguous.
// BM=128 BN=128 BK=32, 256 threads, 8 warps 2(m)x4(n), m16n8k16.
// SMEM word (half2) stride 20 (16 data + 4 pad, =4 mod 32: frag LDS clean).
// modeSel: 0 -> fp32 out (C0); 1 -> QKV set: z0,z1 fp16 natural, z2 V^T scatter.
// ---------------------------------------------------------------------------
#define GW 20
#define GEMM_SMEM_WORDS (2 * 128 * GW * 2)
#define GEMM_SMEM_BYTES (GEMM_SMEM_WORDS * 4)

__global__ __launch_bounds__(256) void gemm_fp16_bias_relu(
    const __half* __restrict__ A,
    const __half* __restrict__ W0, const float* __restrict__ b0, void* __restrict__ C0,
    const __half* __restrict__ W1, const float* __restrict__ b1, void* __restrict__ C1,
    const __half* __restrict__ W2, const float* __restrict__ b2, void* __restrict__ C2,
    int modeSel)
{
    const int N = 1024, K = 1024;
    extern __shared__ unsigned smg[];
    unsigned* As = smg;                  // [2][128][20]
    unsigned* Bs = smg + 2 * 128 * GW;   // [2][128][20]

    const __half* W; const float* bias; void* C;
    if (blockIdx.z == 0)      { W = W0; bias = b0; C = C0; }
    else if (blockIdx.z == 1) { W = W1; bias = b1; C = C1; }
    else                      { W = W2; bias = b2; C = C2; }
    int mode = modeSel ? ((blockIdx.z == 2) ? 2 : 1) : 0;

    int tid  = threadIdx.x;
    int lane = tid & 31;
    int warp = tid >> 5;
    int gid  = lane >> 2;
    int tig  = lane & 3;

    int m0w = (warp & 1) * 64;
    int n0w = (warp >> 1) * 32;

    int rowBase = blockIdx.y * 128;
    int colBase = blockIdx.x * 128;

    // loader coords: 512 cp16 per tile, 2 per thread
    int lr = tid >> 1;             // row 0..127
    int lc = (tid & 1) * 8;        // half offset 0 or 8 within 16-half row... no:
    // per tile: 128 rows x 16 words = 128 rows x 4 cp16 -> idx = tid + v*256
    float acc[4][4][4] = {};

    {
        #pragma unroll
        for (int v = 0; v < 2; v++) {
            int idx = tid + v * 256;
            int r = idx >> 2, cw = (idx & 3) * 4;
            cp_async16(&As[(size_t)r * GW + cw], &A[(size_t)(rowBase + r) * K + cw * 2]);
            cp_async16(&Bs[(size_t)r * GW + cw], &W[(size_t)(colBase + r) * K + cw * 2]);
        }
        cp_commit();
    }

    #pragma unroll 1
    for (int it = 0; it < 32; it++) {
        int buf = it & 1;
        if (it + 1 < 32) {
            int k0n = (it + 1) * 32;
            unsigned* An = As + (buf ^ 1) * 128 * GW;
            unsigned* Bn = Bs + (buf ^ 1) * 128 * GW;
            #pragma unroll
            for (int v = 0; v < 2; v++) {
                int idx = tid + v * 256;
                int r = idx >> 2, cw = (idx & 3) * 4;
                cp_async16(&An[(size_t)r * GW + cw],
                           &A[(size_t)(rowBase + r) * K + k0n + cw * 2]);
                cp_async16(&Bn[(size_t)r * GW + cw],
                           &W[(size_t)(colBase + r) * K + k0n + cw * 2]);
            }
            cp_commit();
            cp_wait<1>();
        } else {
            cp_wait<0>();
        }
        __syncthreads();

        unsigned* Ab = As + buf * 128 * GW;
        unsigned* Bb = Bs + buf * 128 * GW;

        #pragma unroll
        for (int ks = 0; ks < 2; ks++) {
            int kws = ks * 8;
            unsigned af[4][4], bf[4][2];
            #pragma unroll
            for (int mt = 0; mt < 4; mt++) {
                int r = m0w + mt * 16 + gid;
                af[mt][0] = Ab[(size_t)r * GW + kws + tig];
                af[mt][1] = Ab[(size_t)(r + 8) * GW + kws + tig];
                af[mt][2] = Ab[(size_t)r * GW + kws + tig + 4];
                af[mt][3] = Ab[(size_t)(r + 8) * GW + kws + tig + 4];
            }
            #pragma unroll
            for (int nt = 0; nt < 4; nt++) {
                int c = n0w + nt * 8 + gid;
                bf[nt][0] = Bb[(size_t)c * GW + kws + tig];
                bf[nt][1] = Bb[(size_t)c * GW + kws + tig + 4];
            }
            #pragma unroll
            for (int mt = 0; mt < 4; mt++)
                #pragma unroll
                for (int nt = 0; nt < 4; nt++)
                    mma_fp16(acc[mt][nt], af[mt], bf[nt], acc[mt][nt]);
        }
        __syncthreads();
    }

    // epilogue
    #pragma unroll
    for (int mt = 0; mt < 4; mt++) {
        #pragma unroll
        for (int nt = 0; nt < 4; nt++) {
            int col = colBase + n0w + nt * 8 + tig * 2;
            float bv0 = bias[col], bv1 = bias[col + 1];
            int r0 = rowBase + m0w + mt * 16 + gid;
            float v00 = fmaxf(acc[mt][nt][0] + bv0, 0.f);
            float v01 = fmaxf(acc[mt][nt][1] + bv1, 0.f);
            float v10 = fmaxf(acc[mt][nt][2] + bv0, 0.f);
            float v11 = fmaxf(acc[mt][nt][3] + bv1, 0.f);
            if (mode == 0) {
                float* Cf = (float*)C;
                float2 o0, o1;
                o0.x = v00; o0.y = v01;
                o1.x = v10; o1.y = v11;
                *(float2*)&Cf[(size_t)r0 * N + col]       = o0;
                *(float2*)&Cf[(size_t)(r0 + 8) * N + col] = o1;
            } else if (mode == 1) {
                unsigned* Cw = (unsigned*)C;
                Cw[((size_t)r0 * N + col) >> 1]       = pack_half2(v00, v01);
                Cw[((size_t)(r0 + 8) * N + col) >> 1] = pack_half2(v10, v11);
            } else {
                // V^T scatter: [b][h][d][s]
                __half* VT = (__half*)C;
                int b = r0 >> 11, s = r0 & 2047;
                int h = col >> 6, d = col & 63;
                size_t base = ((size_t)(b * NHEAD + h) * DHEAD + d) * SEQ + s;
                VT[base]            = __float2half(v00);
                VT[base + SEQ]      = __float2half(v01);
                VT[base + 8]        = __float2half(v10);
                VT[base + SEQ + 8]  = __float2half(v11);
            }
        }
    }
}

// ---------------------------------------------------------------------------
// fp16 tensor-core flash attention.
// CTA = 128 queries x 1 head x 1 batch, 128 threads = 4 warps; each warp
// owns 32 query rows (2 m16 tiles). m16n8k16 mma everywhere. K SMEM
// [key][d-words], V^T SMEM [d][key-words] (from transposed gmem V), P
// [q][key-words]; all word stride 36 (=4 mod 32, frag LDS conflict-free).
// cp.async double-buffered K/V/mask. Register online softmax. Mask fills
// scaled score with 1e-9 BEFORE softmax.
// ---------------------------------------------------------------------------
#define ATW 36
#define AT_K_WORDS  (2 * 64 * ATW)
#define AT_V_WORDS  (2 * 64 * ATW)
#define AT_P_WORDS  (128 * ATW)
#define AT_SMEM_BYTES ((AT_K_WORDS + AT_V_WORDS + AT_P_WORDS + 2 * 64) * 4)

__global__ __launch_bounds__(128) void attention_mma(
    const __half* __restrict__ Q, const __half* __restrict__ K,
    const __half* __restrict__ VT, const int* __restrict__ mask,
    __half* __restrict__ O)
{
    extern __shared__ unsigned sm[];
    unsigned* Ks  = sm;                        // [2][64][36]
    unsigned* Vs  = Ks + AT_K_WORDS;           // [2][64][36]
    unsigned* Ps  = Vs + AT_V_WORDS;           // [128][36]
    int*      mk  = (int*)(Ps + AT_P_WORDS);   // [2][64]

    int tid  = threadIdx.x;
    int lane = tid & 31;
    int warp = tid >> 5;
    int gid  = lane >> 2;
    int tig  = lane & 3;
    int qt = blockIdx.x;       // 0..15
    int h  = blockIdx.y;
    int b  = blockIdx.z;
    int qbase = qt * 128;
    int m0 = warp * 32;
    const float scale = 0.125f;

    const size_t headOff = (size_t)h * DHEAD;
    const size_t bRow = (size_t)b * SEQ;
    const __half* VTh = VT + (size_t)(b * NHEAD + h) * DHEAD * SEQ;  // [64][2048]

    // loader coords: 512 cp16 per (K or V) tile -> 4 per thread each
    // idx = tid + v*128 : row = idx>>3 (0..63), cw = (idx&7)*4 words
    // K row = key (d contiguous), V row = d (key contiguous)

    // --- Q fragments (fp16 words) ---
    unsigned qf[2][4][4];
    {
        const unsigned* Qw = (const unsigned*)(Q + (bRow + qbase + m0) * DMODEL + headOff);
        #pragma unroll
        for (int mt = 0; mt < 2; mt++) {
            #pragma unroll
            for (int kt = 0; kt < 4; kt++) {
                size_t r0 = (size_t)(mt * 16 + gid) * 512;
                size_t r1 = (size_t)(mt * 16 + gid + 8) * 512;
                qf[mt][kt][0] = Qw[r0 + kt * 8 + tig];
                qf[mt][kt][1] = Qw[r1 + kt * 8 + tig];
                qf[mt][kt][2] = Qw[r0 + kt * 8 + tig + 4];
                qf[mt][kt][3] = Qw[r1 + kt * 8 + tig + 4];
            }
        }
    }

    // --- issue chunk 0 ---
    {
        #pragma unroll
        for (int v = 0; v < 4; v++) {
            int idx = tid + v * 128;
            int row = idx >> 3, cw = (idx & 7) * 4;
            cp_async16(&Ks[(size_t)row * ATW + cw],
                       &K[(bRow + row) * DMODEL + headOff + cw * 2]);
            cp_async16(&Vs[(size_t)row * ATW + cw],
                       &VTh[(size_t)row * SEQ + cw * 2]);
        }
        if (tid < 16) cp_async16(&mk[tid * 4], &mask[bRow + tid * 4]);
        cp_commit();
    }

    float oacc[2][8][4] = {};
    float mS[2][2] = {{-3.0e38f, -3.0e38f}, {-3.0e38f, -3.0e38f}};
    float lS[2][2] = {{0.f, 0.f}, {0.f, 0.f}};

    #pragma unroll 1
    for (int kc = 0; kc < SEQ / 64; kc++) {
        int buf = kc & 1;
        if (kc + 1 < SEQ / 64) {
            int nb = buf ^ 1;
            unsigned* Kn = Ks + nb * 64 * ATW;
            unsigned* Vn = Vs + nb * 64 * ATW;
            #pragma unroll
            for (int v = 0; v < 4; v++) {
                int idx = tid + v * 128;
                int row = idx >> 3, cw = (idx & 7) * 4;
                cp_async16(&Kn[(size_t)row * ATW + cw],
                           &K[(bRow + (kc + 1) * 64 + row) * DMODEL + headOff + cw * 2]);
                cp_async16(&Vn[(size_t)row * ATW + cw],
                           &VTh[(size_t)row * SEQ + (kc + 1) * 64 + cw * 2]);
            }
            if (tid < 16)
                cp_async16(&mk[nb * 64 + tid * 4],
                           &mask[bRow + (kc + 1) * 64 + tid * 4]);
            cp_commit();
            cp_wait<1>();
        } else {
            cp_wait<0>();
        }
        __syncthreads();

        unsigned* Kb = Ks + buf * 64 * ATW;
        unsigned* Vb = Vs + buf * 64 * ATW;
        int* mkb = mk + buf * 64;

        // --- S = Q K^T : 4 k-steps (d) x 8 n-tiles (key) x 2 m-tiles ---
        float s[2][8][4] = {};
        #pragma unroll
        for (int kt = 0; kt < 4; kt++) {
            int kws = kt * 8;
            unsigned bf[8][2];
            #pragma unroll
            for (int nt = 0; nt < 8; nt++) {
                int key = nt * 8 + gid;
                bf[nt][0] = Kb[(size_t)key * ATW + kws + tig];
                bf[nt][1] = Kb[(size_t)key * ATW + kws + tig + 4];
            }
            #pragma unroll
            for (int nt = 0; nt < 8; nt++) {
                mma_fp16(s[0][nt], qf[0][kt], bf[nt], s[0][nt]);
                mma_fp16(s[1][nt], qf[1][kt], bf[nt], s[1][nt]);
            }
        }

        // --- mask + scale + online softmax (4 rows/thread) ---
        float mnew[2][2] = {{mS[0][0], mS[0][1]}, {mS[1][0], mS[1][1]}};
        #pragma unroll
        for (int nt = 0; nt < 8; nt++) {
            int c = nt * 8 + 2 * tig;
            bool k0m = (mkb[c] != 0), k1m = (mkb[c + 1] != 0);
            #pragma unroll
            for (int mt = 0; mt < 2; mt++) {
                s[mt][nt][0] = k0m ? 1e-9f : s[mt][nt][0] * scale;
                s[mt][nt][1] = k1m ? 1e-9f : s[mt][nt][1] * scale;
                s[mt][nt][2] = k0m ? 1e-9f : s[mt][nt][2] * scale;
                s[mt][nt][3] = k1m ? 1e-9f : s[mt][nt][3] * scale;
                mnew[mt][0] = fmaxf(mnew[mt][0], fmaxf(s[mt][nt][0], s[mt][nt][1]));
                mnew[mt][1] = fmaxf(mnew[mt][1], fmaxf(s[mt][nt][2], s[mt][nt][3]));
            }
        }
        #pragma unroll
        for (int mt = 0; mt < 2; mt++)
            #pragma unroll
            for (int hh = 0; hh < 2; hh++) {
                mnew[mt][hh] = fmaxf(mnew[mt][hh],
                                     __shfl_xor_sync(0xffffffff, mnew[mt][hh], 1));
                mnew[mt][hh] = fmaxf(mnew[mt][hh],
                                     __shfl_xor_sync(0xffffffff, mnew[mt][hh], 2));
            }

        float alpha[2][2];
        #pragma unroll
        for (int mt = 0; mt < 2; mt++)
            #pragma unroll
            for (int hh = 0; hh < 2; hh++) {
                alpha[mt][hh] = __expf(mS[mt][hh] - mnew[mt][hh]);
                mS[mt][hh] = mnew[mt][hh];
            }

        #pragma unroll
        for (int mt = 0; mt < 2; mt++) {
            float sum0 = 0.f, sum1 = 0.f;
            int prow0 = (m0 + mt * 16 + gid) * ATW;
            int prow1 = (m0 + mt * 16 + gid + 8) * ATW;
            #pragma unroll
            for (int nt = 0; nt < 8; nt++) {
                float p0 = __expf(s[mt][nt][0] - mnew[mt][0]);
                float p1 = __expf(s[mt][nt][1] - mnew[mt][0]);
                float p2 = __expf(s[mt][nt][2] - mnew[mt][1]);
                float p3 = __expf(s[mt][nt][3] - mnew[mt][1]);
                sum0 += p0 + p1;
                sum1 += p2 + p3;
                Ps[prow0 + nt * 4 + tig] = pack_half2(p0, p1);
                Ps[prow1 + nt * 4 + tig] = pack_half2(p2, p3);
            }
            sum0 += __shfl_xor_sync(0xffffffff, sum0, 1);
            sum0 += __shfl_xor_sync(0xffffffff, sum0, 2);
            sum1 += __shfl_xor_sync(0xffffffff, sum1, 1);
            sum1 += __shfl_xor_sync(0xffffffff, sum1, 2);
            lS[mt][0] = lS[mt][0] * alpha[mt][0] + sum0;
            lS[mt][1] = lS[mt][1] * alpha[mt][1] + sum1;
            #pragma unroll
            for (int dt = 0; dt < 8; dt++) {
                oacc[mt][dt][0] *= alpha[mt][0];
                oacc[mt][dt][1] *= alpha[mt][0];
                oacc[mt][dt][2] *= alpha[mt][1];
                oacc[mt][dt][3] *= alpha[mt][1];
            }
        }

        __syncwarp();   // Ps rows are warp-private

        // --- O += P V : 4 k-steps (key) x 8 d-tiles x 2 m-tiles ---
        #pragma unroll
        for (int kk = 0; kk < 4; kk++) {
            int kws = kk * 8;
            unsigned af0[4], af1[4];
            {
                int p00 = (m0 + gid) * ATW;
                int p01 = (m0 + gid + 8) * ATW;
                int p10 = (m0 + 16 + gid) * ATW;
                int p11 = (m0 + 16 + gid + 8) * ATW;
                af0[0] = Ps[p00 + kws + tig];
                af0[1] = Ps[p01 + kws + tig];
                af0[2] = Ps[p00 + kws + tig + 4];
                af0[3] = Ps[p01 + kws + tig + 4];
                af1[0] = Ps[p10 + kws + tig];
                af1[1] = Ps[p11 + kws + tig];
                af1[2] = Ps[p10 + kws + tig + 4];
                af1[3] = Ps[p11 + kws + tig + 4];
            }
            unsigned bf[8][2];
            #pragma unroll
            for (int dt = 0; dt < 8; dt++) {
                int d = dt * 8 + gid;
                bf[dt][0] = Vb[(size_t)d * ATW + kws + tig];
                bf[dt][1] = Vb[(size_t)d * ATW + kws + tig + 4];
            }
            #pragma unroll
            for (int dt = 0; dt < 8; dt++) {
                mma_fp16(oacc[0][dt], af0, bf[dt], oacc[0][dt]);
                mma_fp16(oacc[1][dt], af1, bf[dt], oacc[1][dt]);
            }
        }
        __syncthreads();   // K/V buffers reused by next iter's cp.async
    }

    // --- epilogue: normalize + store fp16 (consumed only by out-proj mma) ---
    unsigned* Ow = (unsigned*)O;
    #pragma unroll
    for (int mt = 0; mt < 2; mt++) {
        float inv0 = 1.f / lS[mt][0];
        float inv1 = 1.f / lS[mt][1];
        size_t r0 = ((bRow + qbase + m0 + mt * 16 + gid) * DMODEL + headOff) >> 1;
        size_t r1 = ((bRow + qbase + m0 + mt * 16 + gid + 8) * DMODEL + headOff) >> 1;
        #pragma unroll
        for (int dt = 0; dt < 8; dt++) {
            int cw = dt * 4 + tig;
            Ow[r0 + cw] = pack_half2(oacc[mt][dt][0] * inv0, oacc[mt][dt][1] * inv0);
            Ow[r1 + cw] = pack_half2(oacc[mt][dt][2] * inv1, oacc[mt][dt][3] * inv1);
        }
    }
}

// ---------------------------------------------------------------------------
// launch
// ---------------------------------------------------------------------------
extern "C" void kernel_launch(void* const* d_in, const int* in_sizes, int n_in,
                              void* d_out, int out_size)
{
    const float* x    = (const float*)d_in[0];
    const int*   mask = (const int*)  d_in[1];
    const float* Wq   = (const float*)d_in[2];
    const float* bq   = (const float*)d_in[3];
    const float* Wk   = (const float*)d_in[4];
    const float* bk   = (const float*)d_in[5];
    const float* Wv   = (const float*)d_in[6];
    const float* bv   = (const float*)d_in[7];
    const float* Wo   = (const float*)d_in[8];
    const float* bo   = (const float*)d_in[9];
    float* out = (float*)d_out;

    __half *xh, *Wqh, *Wkh, *Wvh, *Woh, *Qp, *Kp, *Vp, *AOp;
    cudaGetSymbolAddress((void**)&xh,  g_xh);
    cudaGetSymbolAddress((void**)&Wqh, g_Wqh);
    cudaGetSymbolAddress((void**)&Wkh, g_Wkh);
    cudaGetSymbolAddress((void**)&Wvh, g_Wvh);
    cudaGetSymbolAddress((void**)&Woh, g_Woh);
    cudaGetSymbolAddress((void**)&Qp,  g_Q);
    cudaGetSymbolAddress((void**)&Kp,  g_K);
    cudaGetSymbolAddress((void**)&Vp,  g_V);
    cudaGetSymbolAddress((void**)&AOp, g_AO);

    cudaFuncSetAttribute(gemm_fp16_bias_relu,
                         cudaFuncAttributeMaxDynamicSharedMemorySize, GEMM_SMEM_BYTES);
    cudaFuncSetAttribute(attention_mma,
                         cudaFuncAttributeMaxDynamicSharedMemorySize, AT_SMEM_BYTES);

    // convert inputs
    cvt_x_fp16<<<MROWS * DMODEL / 8 / 256, 256>>>(x, xh);
    cvt_w_t<<<dim3(32, 32, 4), dim3(32, 8)>>>(Wq, Wk, Wv, Wo);

    // fused Q/K/V projections (Q,K natural fp16; V transposed fp16)
    dim3 gqkv(1024 / 128, 4096 / 128, 3);
    gemm_fp16_bias_relu<<<gqkv, 256, GEMM_SMEM_BYTES>>>(xh,
                                       Wqh, bq, Qp,
                                       Wkh, bk, Kp,
                                       Wvh, bv, Vp, 1);

    attention_mma<<<dim3(SEQ / 128, NHEAD, BATCH), 128, AT_SMEM_BYTES>>>(
        Qp, Kp, Vp, mask, AOp);

    // output projection (fp32 store)
    dim3 go(1024 / 128, 4096 / 128, 1);
    gemm_fp16_bias_relu<<<go, 256, GEMM_SMEM_BYTES>>>(AOp,
                                     Woh, bo, out,
                                     Woh, bo, out,
                                     Woh, bo, out, 0);
}

// round 11
// speedup vs baseline: 7.4145x; 1.0743x over previous
#include <cuda_runtime.h>
#include <cuda_fp16.h>
#include <math.h>

// Problem constants
#define BATCH 2
#define SEQ   2048
#define DMODEL 1024
#define NHEAD 16
#define DHEAD 64
#define MROWS (BATCH * SEQ)   // 4096

// Scratch (allocation-free rule: __device__ globals)
__device__ __half g_xh [MROWS * DMODEL];         // x  fp16 [row][k]
__device__ __half g_Wqh[DMODEL * DMODEL];        // Wq^T fp16 [n][k]
__device__ __half g_Wkh[DMODEL * DMODEL];
__device__ __half g_Wvh[DMODEL * DMODEL];
__device__ __half g_Woh[DMODEL * DMODEL];
__device__ __half g_Q  [MROWS * DMODEL];         // fp16 [row][h*64+d]
__device__ __half g_K  [MROWS * DMODEL];         // fp16 [row][h*64+d]
__device__ __half g_V  [MROWS * DMODEL];         // fp16 TRANSPOSED [b][h][d][s]
__device__ __half g_AO [MROWS * DMODEL];         // fp16 [row][h*64+d]

// ---------------------------------------------------------------------------
// helpers
// ---------------------------------------------------------------------------
__device__ __forceinline__ unsigned pack_half2(float a, float b) {
    __half2 h = __floats2half2_rn(a, b);
    return *(unsigned*)&h;
}

__device__ __forceinline__ void mma_fp16(
    float* d, const unsigned* a, const unsigned* b, const float* c)
{
    asm volatile(
        "mma.sync.aligned.m16n8k16.row.col.f32.f16.f16.f32 "
        "{%0,%1,%2,%3}, {%4,%5,%6,%7}, {%8,%9}, {%10,%11,%12,%13};\n"
        : "=f"(d[0]), "=f"(d[1]), "=f"(d[2]), "=f"(d[3])
        : "r"(a[0]), "r"(a[1]), "r"(a[2]), "r"(a[3]),
          "r"(b[0]), "r"(b[1]),
          "f"(c[0]), "f"(c[1]), "f"(c[2]), "f"(c[3]));
}

__device__ __forceinline__ void ldsm_x4(unsigned* r, unsigned addr) {
    asm volatile(
        "ldmatrix.sync.aligned.m8n8.x4.shared.b16 {%0,%1,%2,%3}, [%4];\n"
        : "=r"(r[0]), "=r"(r[1]), "=r"(r[2]), "=r"(r[3]) : "r"(addr));
}

__device__ __forceinline__ void cp_async16(void* smem_ptr, const void* gmem_ptr) {
    unsigned saddr = (unsigned)__cvta_generic_to_shared(smem_ptr);
    asm volatile("cp.async.cg.shared.global [%0], [%1], 16;\n"
                 :: "r"(saddr), "l"(gmem_ptr));
}
__device__ __forceinline__ void cp_commit() {
    asm volatile("cp.async.commit_group;\n");
}
template<int N> __device__ __forceinline__ void cp_wait() {
    asm volatile("cp.async.wait_group %0;\n" :: "n"(N));
}

// ---------------------------------------------------------------------------
// cvt x -> fp16 (identity layout)
// ---------------------------------------------------------------------------
__global__ __launch_bounds__(256) void cvt_x_fp16(
    const float* __restrict__ x, __half* __restrict__ xh)
{
    int i = blockIdx.x * 256 + threadIdx.x;
    float4 v0 = *(const float4*)&x[(size_t)i * 8];
    float4 v1 = *(const float4*)&x[(size_t)i * 8 + 4];
    uint4 u;
    u.x = pack_half2(v0.x, v0.y);
    u.y = pack_half2(v0.z, v0.w);
    u.z = pack_half2(v1.x, v1.y);
    u.w = pack_half2(v1.z, v1.w);
    *(uint4*)&xh[(size_t)i * 8] = u;
}

// ---------------------------------------------------------------------------
// transpose + cvt weights: W[k][n] fp32 -> WT[n][k] fp16
// ---------------------------------------------------------------------------
__global__ __launch_bounds__(256) void cvt_w_t(
    const float* __restrict__ wq, const float* __restrict__ wk,
    const float* __restrict__ wv, const float* __restrict__ wo)
{
    __shared__ __half tile[32][33];
    const float* W; __half* WT;
    if (blockIdx.z == 0)      { W = wq; WT = g_Wqh; }
    else if (blockIdx.z == 1) { W = wk; WT = g_Wkh; }
    else if (blockIdx.z == 2) { W = wv; WT = g_Wvh; }
    else                      { W = wo; WT = g_Woh; }

    int tx = threadIdx.x, ty = threadIdx.y;
    int bx = blockIdx.x * 32, by = blockIdx.y * 32;
    #pragma unroll
    for (int j = 0; j < 4; j++) {
        int r = by + ty + j * 8;
        tile[ty + j * 8][tx] = __float2half(W[(size_t)r * DMODEL + bx + tx]);
    }
    __syncthreads();
    #pragma unroll
    for (int j = 0; j < 4; j++) {
        int r = bx + ty + j * 8;
        WT[(size_t)r * DMODEL + by + tx] = tile[tx][ty + j * 8];
    }
}

// ---------------------------------------------------------------------------
// fp16 GEMM with ldmatrix fragment loads, cp.async double-buffered.
// C = relu(A @ WT' + bias). BM=128 BN=128 BK=32, 256 threads, 8 warps
// 2(m)x4(n), m16n8k16. SMEM word stride 20.
// ---------------------------------------------------------------------------
#define GW 20
#define GEMM_SMEM_WORDS (2 * 128 * GW * 2)
#define GEMM_SMEM_BYTES (GEMM_SMEM_WORDS * 4)

__global__ __launch_bounds__(256) void gemm_fp16_bias_relu(
    const __half* __restrict__ A,
    const __half* __restrict__ W0, const float* __restrict__ b0, void* __restrict__ C0,
    const __half* __restrict__ W1, const float* __restrict__ b1, void* __restrict__ C1,
    const __half* __restrict__ W2, const float* __restrict__ b2, void* __restrict__ C2,
    int modeSel)
{
    const int N = 1024, K = 1024;
    extern __shared__ unsigned smg[];
    unsigned* As = smg;                  // [2][128][20]
    unsigned* Bs = smg + 2 * 128 * GW;   // [2][128][20]

    const __half* W; const float* bias; void* C;
    if (blockIdx.z == 0)      { W = W0; bias = b0; C = C0; }
    else if (blockIdx.z == 1) { W = W1; bias = b1; C = C1; }
    else                      { W = W2; bias = b2; C = C2; }
    int mode = modeSel ? ((blockIdx.z == 2) ? 2 : 1) : 0;

    int tid  = threadIdx.x;
    int lane = tid & 31;
    int warp = tid >> 5;
    int gid  = lane >> 2;
    int tig  = lane & 3;
    int l8   = lane & 7;
    int tile = lane >> 3;

    int m0w = (warp & 1) * 64;
    int n0w = (warp >> 1) * 32;

    int rowBase = blockIdx.y * 128;
    int colBase = blockIdx.x * 128;

    unsigned smem_u = (unsigned)__cvta_generic_to_shared(smg);
    unsigned as_u = smem_u;
    unsigned bs_u = smem_u + 2 * 128 * GW * 4;
    // ldmatrix lane offsets (bytes)
    unsigned aoff = (((tile & 1) * 8 + l8) * GW + (tile >> 1) * 4) * 4;
    unsigned boff = (((tile >> 1) * 8 + l8) * GW + (tile & 1) * 4) * 4;

    float acc[4][4][4] = {};

    {
        #pragma unroll
        for (int v = 0; v < 2; v++) {
            int idx = tid + v * 256;
            int r = idx >> 2, cw = (idx & 3) * 4;
            cp_async16(&As[(size_t)r * GW + cw], &A[(size_t)(rowBase + r) * K + cw * 2]);
            cp_async16(&Bs[(size_t)r * GW + cw], &W[(size_t)(colBase + r) * K + cw * 2]);
        }
        cp_commit();
    }

    #pragma unroll 1
    for (int it = 0; it < 32; it++) {
        int buf = it & 1;
        if (it + 1 < 32) {
            int k0n = (it + 1) * 32;
            unsigned* An = As + (buf ^ 1) * 128 * GW;
            unsigned* Bn = Bs + (buf ^ 1) * 128 * GW;
            #pragma unroll
            for (int v = 0; v < 2; v++) {
                int idx = tid + v * 256;
                int r = idx >> 2, cw = (idx & 3) * 4;
                cp_async16(&An[(size_t)r * GW + cw],
                           &A[(size_t)(rowBase + r) * K + k0n + cw * 2]);
                cp_async16(&Bn[(size_t)r * GW + cw],
                           &W[(size_t)(colBase + r) * K + k0n + cw * 2]);
            }
            cp_commit();
            cp_wait<1>();
        } else {
            cp_wait<0>();
        }
        __syncthreads();

        unsigned ab_u = as_u + buf * 128 * GW * 4;
        unsigned bb_u = bs_u + buf * 128 * GW * 4;

        #pragma unroll
        for (int ks = 0; ks < 2; ks++) {
            unsigned af[4][4], bf[2][4];
            #pragma unroll
            for (int mt = 0; mt < 4; mt++)
                ldsm_x4(af[mt], ab_u + (((m0w + mt * 16) * GW + ks * 8) * 4) + aoff);
            ldsm_x4(bf[0], bb_u + (((n0w     ) * GW + ks * 8) * 4) + boff);
            ldsm_x4(bf[1], bb_u + (((n0w + 16) * GW + ks * 8) * 4) + boff);
            #pragma unroll
            for (int mt = 0; mt < 4; mt++) {
                mma_fp16(acc[mt][0], af[mt], &bf[0][0], acc[mt][0]);
                mma_fp16(acc[mt][1], af[mt], &bf[0][2], acc[mt][1]);
                mma_fp16(acc[mt][2], af[mt], &bf[1][0], acc[mt][2]);
                mma_fp16(acc[mt][3], af[mt], &bf[1][2], acc[mt][3]);
            }
        }
        __syncthreads();
    }

    // epilogue
    #pragma unroll
    for (int mt = 0; mt < 4; mt++) {
        #pragma unroll
        for (int nt = 0; nt < 4; nt++) {
            int col = colBase + n0w + nt * 8 + tig * 2;
            float bv0 = bias[col], bv1 = bias[col + 1];
            int r0 = rowBase + m0w + mt * 16 + gid;
            float v00 = fmaxf(acc[mt][nt][0] + bv0, 0.f);
            float v01 = fmaxf(acc[mt][nt][1] + bv1, 0.f);
            float v10 = fmaxf(acc[mt][nt][2] + bv0, 0.f);
            float v11 = fmaxf(acc[mt][nt][3] + bv1, 0.f);
            if (mode == 0) {
                float* Cf = (float*)C;
                float2 o0, o1;
                o0.x = v00; o0.y = v01;
                o1.x = v10; o1.y = v11;
                *(float2*)&Cf[(size_t)r0 * N + col]       = o0;
                *(float2*)&Cf[(size_t)(r0 + 8) * N + col] = o1;
            } else if (mode == 1) {
                unsigned* Cw = (unsigned*)C;
                Cw[((size_t)r0 * N + col) >> 1]       = pack_half2(v00, v01);
                Cw[((size_t)(r0 + 8) * N + col) >> 1] = pack_half2(v10, v11);
            } else {
                // V^T scatter: [b][h][d][s]
                __half* VT = (__half*)C;
                int b = r0 >> 11, s = r0 & 2047;
                int h = col >> 6, d = col & 63;
                size_t base = ((size_t)(b * NHEAD + h) * DHEAD + d) * SEQ + s;
                VT[base]            = __float2half(v00);
                VT[base + SEQ]      = __float2half(v01);
                VT[base + 8]        = __float2half(v10);
                VT[base + SEQ + 8]  = __float2half(v11);
            }
        }
    }
}

// ---------------------------------------------------------------------------
// fp16 flash attention with ldmatrix fragment loads.
// CTA = 128 q x 1 head x 1 batch, 128 threads = 4 warps; warp owns 32 q
// rows (2 m16 tiles). K SMEM [key][d-words], V^T SMEM [d][key-words],
// P [q][key-words], all word stride 36. cp.async double-buffered.
// Register online softmax; mask fill 1e-9 BEFORE softmax.
// ---------------------------------------------------------------------------
#define ATW 36
#define AT_K_WORDS  (2 * 64 * ATW)
#define AT_V_WORDS  (2 * 64 * ATW)
#define AT_P_WORDS  (128 * ATW)
#define AT_SMEM_BYTES ((AT_K_WORDS + AT_V_WORDS + AT_P_WORDS + 2 * 64) * 4)

__global__ __launch_bounds__(128) void attention_mma(
    const __half* __restrict__ Q, const __half* __restrict__ K,
    const __half* __restrict__ VT, const int* __restrict__ mask,
    __half* __restrict__ O)
{
    extern __shared__ unsigned sm[];
    unsigned* Ks  = sm;                        // [2][64][36]
    unsigned* Vs  = Ks + AT_K_WORDS;           // [2][64][36]
    unsigned* Ps  = Vs + AT_V_WORDS;           // [128][36]
    int*      mk  = (int*)(Ps + AT_P_WORDS);   // [2][64]

    int tid  = threadIdx.x;
    int lane = tid & 31;
    int warp = tid >> 5;
    int gid  = lane >> 2;
    int tig  = lane & 3;
    int l8   = lane & 7;
    int tile = lane >> 3;
    int qt = blockIdx.x;
    int h  = blockIdx.y;
    int b  = blockIdx.z;
    int qbase = qt * 128;
    int m0 = warp * 32;
    const float scale = 0.125f;

    const size_t headOff = (size_t)h * DHEAD;
    const size_t bRow = (size_t)b * SEQ;
    const __half* VTh = VT + (size_t)(b * NHEAD + h) * DHEAD * SEQ;

    unsigned smem_u = (unsigned)__cvta_generic_to_shared(sm);
    unsigned ks_u = smem_u;
    unsigned vs_u = smem_u + AT_K_WORDS * 4;
    unsigned ps_u = smem_u + (AT_K_WORDS + AT_V_WORDS) * 4;
    unsigned boff = (((tile >> 1) * 8 + l8) * ATW + (tile & 1) * 4) * 4;
    unsigned aoff = (((tile & 1) * 8 + l8) * ATW + (tile >> 1) * 4) * 4;

    // --- Q fragments (fp16 words) ---
    unsigned qf[2][4][4];
    {
        const unsigned* Qw = (const unsigned*)(Q + (bRow + qbase + m0) * DMODEL + headOff);
        #pragma unroll
        for (int mt = 0; mt < 2; mt++) {
            #pragma unroll
            for (int kt = 0; kt < 4; kt++) {
                size_t r0 = (size_t)(mt * 16 + gid) * 512;
                size_t r1 = (size_t)(mt * 16 + gid + 8) * 512;
                qf[mt][kt][0] = Qw[r0 + kt * 8 + tig];
                qf[mt][kt][1] = Qw[r1 + kt * 8 + tig];
                qf[mt][kt][2] = Qw[r0 + kt * 8 + tig + 4];
                qf[mt][kt][3] = Qw[r1 + kt * 8 + tig + 4];
            }
        }
    }

    // --- issue chunk 0 ---
    {
        #pragma unroll
        for (int v = 0; v < 4; v++) {
            int idx = tid + v * 128;
            int row = idx >> 3, cw = (idx & 7) * 4;
            cp_async16(&Ks[(size_t)row * ATW + cw],
                       &K[(bRow + row) * DMODEL + headOff + cw * 2]);
            cp_async16(&Vs[(size_t)row * ATW + cw],
                       &VTh[(size_t)row * SEQ + cw * 2]);
        }
        if (tid < 16) cp_async16(&mk[tid * 4], &mask[bRow + tid * 4]);
        cp_commit();
    }

    float oacc[2][8][4] = {};
    float mS[2][2] = {{-3.0e38f, -3.0e38f}, {-3.0e38f, -3.0e38f}};
    float lS[2][2] = {{0.f, 0.f}, {0.f, 0.f}};

    #pragma unroll 1
    for (int kc = 0; kc < SEQ / 64; kc++) {
        int buf = kc & 1;
        if (kc + 1 < SEQ / 64) {
            int nb = buf ^ 1;
            unsigned* Kn = Ks + nb * 64 * ATW;
            unsigned* Vn = Vs + nb * 64 * ATW;
            #pragma unroll
            for (int v = 0; v < 4; v++) {
                int idx = tid + v * 128;
                int row = idx >> 3, cw = (idx & 7) * 4;
                cp_async16(&Kn[(size_t)row * ATW + cw],
                           &K[(bRow + (kc + 1) * 64 + row) * DMODEL + headOff + cw * 2]);
                cp_async16(&Vn[(size_t)row * ATW + cw],
                           &VTh[(size_t)row * SEQ + (kc + 1) * 64 + cw * 2]);
            }
            if (tid < 16)
                cp_async16(&mk[nb * 64 + tid * 4],
                           &mask[bRow + (kc + 1) * 64 + tid * 4]);
            cp_commit();
            cp_wait<1>();
        } else {
            cp_wait<0>();
        }
        __syncthreads();

        unsigned kb_u = ks_u + buf * 64 * ATW * 4;
        unsigned vb_u = vs_u + buf * 64 * ATW * 4;
        int* mkb = mk + buf * 64;

        // --- S = Q K^T : ldmatrix B-frags, 2 n-tiles per ldsm ---
        float s[2][8][4] = {};
        #pragma unroll
        for (int kt = 0; kt < 4; kt++) {
            #pragma unroll
            for (int j = 0; j < 4; j++) {
                unsigned bq[4];
                ldsm_x4(bq, kb_u + ((j * 16 * ATW + kt * 8) * 4) + boff);
                mma_fp16(s[0][2*j],     qf[0][kt], &bq[0], s[0][2*j]);
                mma_fp16(s[1][2*j],     qf[1][kt], &bq[0], s[1][2*j]);
                mma_fp16(s[0][2*j + 1], qf[0][kt], &bq[2], s[0][2*j + 1]);
                mma_fp16(s[1][2*j + 1], qf[1][kt], &bq[2], s[1][2*j + 1]);
            }
        }

        // --- mask + scale + online softmax (4 rows/thread) ---
        float mnew[2][2] = {{mS[0][0], mS[0][1]}, {mS[1][0], mS[1][1]}};
        #pragma unroll
        for (int nt = 0; nt < 8; nt++) {
            int c = nt * 8 + 2 * tig;
            bool k0m = (mkb[c] != 0), k1m = (mkb[c + 1] != 0);
            #pragma unroll
            for (int mt = 0; mt < 2; mt++) {
                s[mt][nt][0] = k0m ? 1e-9f : s[mt][nt][0] * scale;
                s[mt][nt][1] = k1m ? 1e-9f : s[mt][nt][1] * scale;
                s[mt][nt][2] = k0m ? 1e-9f : s[mt][nt][2] * scale;
                s[mt][nt][3] = k1m ? 1e-9f : s[mt][nt][3] * scale;
                mnew[mt][0] = fmaxf(mnew[mt][0], fmaxf(s[mt][nt][0], s[mt][nt][1]));
                mnew[mt][1] = fmaxf(mnew[mt][1], fmaxf(s[mt][nt][2], s[mt][nt][3]));
            }
        }
        #pragma unroll
        for (int mt = 0; mt < 2; mt++)
            #pragma unroll
            for (int hh = 0; hh < 2; hh++) {
                mnew[mt][hh] = fmaxf(mnew[mt][hh],
                                     __shfl_xor_sync(0xffffffff, mnew[mt][hh], 1));
                mnew[mt][hh] = fmaxf(mnew[mt][hh],
                                     __shfl_xor_sync(0xffffffff, mnew[mt][hh], 2));
            }

        float alpha[2][2];
        #pragma unroll
        for (int mt = 0; mt < 2; mt++)
            #pragma unroll
            for (int hh = 0; hh < 2; hh++) {
                alpha[mt][hh] = __expf(mS[mt][hh] - mnew[mt][hh]);
                mS[mt][hh] = mnew[mt][hh];
            }

        #pragma unroll
        for (int mt = 0; mt < 2; mt++) {
            float sum0 = 0.f, sum1 = 0.f;
            int prow0 = (m0 + mt * 16 + gid) * ATW;
            int prow1 = (m0 + mt * 16 + gid + 8) * ATW;
            #pragma unroll
            for (int nt = 0; nt < 8; nt++) {
                float p0 = __expf(s[mt][nt][0] - mnew[mt][0]);
                float p1 = __expf(s[mt][nt][1] - mnew[mt][0]);
                float p2 = __expf(s[mt][nt][2] - mnew[mt][1]);
                float p3 = __expf(s[mt][nt][3] - mnew[mt][1]);
                sum0 += p0 + p1;
                sum1 += p2 + p3;
                Ps[prow0 + nt * 4 + tig] = pack_half2(p0, p1);
                Ps[prow1 + nt * 4 + tig] = pack_half2(p2, p3);
            }
            sum0 += __shfl_xor_sync(0xffffffff, sum0, 1);
            sum0 += __shfl_xor_sync(0xffffffff, sum0, 2);
            sum1 += __shfl_xor_sync(0xffffffff, sum1, 1);
            sum1 += __shfl_xor_sync(0xffffffff, sum1, 2);
            lS[mt][0] = lS[mt][0] * alpha[mt][0] + sum0;
            lS[mt][1] = lS[mt][1] * alpha[mt][1] + sum1;
            #pragma unroll
            for (int dt = 0; dt < 8; dt++) {
                oacc[mt][dt][0] *= alpha[mt][0];
                oacc[mt][dt][1] *= alpha[mt][0];
                oacc[mt][dt][2] *= alpha[mt][1];
                oacc[mt][dt][3] *= alpha[mt][1];
            }
        }

        __syncwarp();   // Ps rows are warp-private

        // --- O += P V : ldmatrix A- and B-frags ---
        #pragma unroll
        for (int kk = 0; kk < 4; kk++) {
            unsigned af0[4], af1[4];
            ldsm_x4(af0, ps_u + (((m0     ) * ATW + kk * 8) * 4) + aoff);
            ldsm_x4(af1, ps_u + (((m0 + 16) * ATW + kk * 8) * 4) + aoff);
            #pragma unroll
            for (int j = 0; j < 4; j++) {
                unsigned bv[4];
                ldsm_x4(bv, vb_u + ((j * 16 * ATW + kk * 8) * 4) + boff);
                mma_fp16(oacc[0][2*j],     af0, &bv[0], oacc[0][2*j]);
                mma_fp16(oacc[1][2*j],     af1, &bv[0], oacc[1][2*j]);
                mma_fp16(oacc[0][2*j + 1], af0, &bv[2], oacc[0][2*j + 1]);
                mma_fp16(oacc[1][2*j + 1], af1, &bv[2], oacc[1][2*j + 1]);
            }
        }
        __syncthreads();   // K/V buffers reused by next iter's cp.async
    }

    // --- epilogue: normalize + store fp16 ---
    unsigned* Ow = (unsigned*)O;
    #pragma unroll
    for (int mt = 0; mt < 2; mt++) {
        float inv0 = 1.f / lS[mt][0];
        float inv1 = 1.f / lS[mt][1];
        size_t r0 = ((bRow + qbase + m0 + mt * 16 + gid) * DMODEL + headOff) >> 1;
        size_t r1 = ((bRow + qbase + m0 + mt * 16 + gid + 8) * DMODEL + headOff) >> 1;
        #pragma unroll
        for (int dt = 0; dt < 8; dt++) {
            int cw = dt * 4 + tig;
            Ow[r0 + cw] = pack_half2(oacc[mt][dt][0] * inv0, oacc[mt][dt][1] * inv0);
            Ow[r1 + cw] = pack_half2(oacc[mt][dt][2] * inv1, oacc[mt][dt][3] * inv1);
        }
    }
}

// ---------------------------------------------------------------------------
// launch
// ---------------------------------------------------------------------------
extern "C" void kernel_launch(void* const* d_in, const int* in_sizes, int n_in,
                              void* d_out, int out_size)
{
    const float* x    = (const float*)d_in[0];
    const int*   mask = (const int*)  d_in[1];
    const float* Wq   = (const float*)d_in[2];
    const float* bq   = (const float*)d_in[3];
    const float* Wk   = (const float*)d_in[4];
    const float* bk   = (const float*)d_in[5];
    const float* Wv   = (const float*)d_in[6];
    const float* bv   = (const float*)d_in[7];
    const float* Wo   = (const float*)d_in[8];
    const float* bo   = (const float*)d_in[9];
    float* out = (float*)d_out;

    __half *xh, *Wqh, *Wkh, *Wvh, *Woh, *Qp, *Kp, *Vp, *AOp;
    cudaGetSymbolAddress((void**)&xh,  g_xh);
    cudaGetSymbolAddress((void**)&Wqh, g_Wqh);
    cudaGetSymbolAddress((void**)&Wkh, g_Wkh);
    cudaGetSymbolAddress((void**)&Wvh, g_Wvh);
    cudaGetSymbolAddress((void**)&Woh, g_Woh);
    cudaGetSymbolAddress((void**)&Qp,  g_Q);
    cudaGetSymbolAddress((void**)&Kp,  g_K);
    cudaGetSymbolAddress((void**)&Vp,  g_V);
    cudaGetSymbolAddress((void**)&AOp, g_AO);

    cudaFuncSetAttribute(gemm_fp16_bias_relu,
                         cudaFuncAttributeMaxDynamicSharedMemorySize, GEMM_SMEM_BYTES);
    cudaFuncSetAttribute(attention_mma,
                         cudaFuncAttributeMaxDynamicSharedMemorySize, AT_SMEM_BYTES);

    // convert inputs
    cvt_x_fp16<<<MROWS * DMODEL / 8 / 256, 256>>>(x, xh);
    cvt_w_t<<<dim3(32, 32, 4), dim3(32, 8)>>>(Wq, Wk, Wv, Wo);

    // fused Q/K/V projections (Q,K natural fp16; V transposed fp16)
    dim3 gqkv(1024 / 128, 4096 / 128, 3);
    gemm_fp16_bias_relu<<<gqkv, 256, GEMM_SMEM_BYTES>>>(xh,
                                       Wqh, bq, Qp,
                                       Wkh, bk, Kp,
                                       Wvh, bv, Vp, 1);

    attention_mma<<<dim3(SEQ / 128, NHEAD, BATCH), 128, AT_SMEM_BYTES>>>(
        Qp, Kp, Vp, mask, AOp);

    // output projection (fp32 store)
    dim3 go(1024 / 128, 4096 / 128, 1);
    gemm_fp16_bias_relu<<<go, 256, GEMM_SMEM_BYTES>>>(AOp,
                                     Woh, bo, out,
                                     Woh, bo, out,
                                     Woh, bo, out, 0);
}

// round 12
// speedup vs baseline: 8.5421x; 1.1521x over previous
#include <cuda_runtime.h>
#include <cuda_fp16.h>
#include <math.h>

// Problem constants
#define BATCH 2
#define SEQ   2048
#define DMODEL 1024
#define NHEAD 16
#define DHEAD 64
#define MROWS (BATCH * SEQ)   // 4096

// Scratch (allocation-free rule: __device__ globals)
__device__ __half g_xh [MROWS * DMODEL];         // x  fp16 [row][k]
__device__ __half g_Wqh[DMODEL * DMODEL];        // Wq^T fp16 [n][k]
__device__ __half g_Wkh[DMODEL * DMODEL];
__device__ __half g_Wvh[DMODEL * DMODEL];
__device__ __half g_Woh[DMODEL * DMODEL];
__device__ __half g_Q  [MROWS * DMODEL];         // fp16 [row][h*64+d]
__device__ __half g_K  [MROWS * DMODEL];         // fp16 [row][h*64+d]
__device__ __half g_V  [MROWS * DMODEL];         // fp16 TRANSPOSED [b][h][d][s]
__device__ __half g_AO [MROWS * DMODEL];         // fp16 [row][h*64+d]

// ---------------------------------------------------------------------------
// helpers
// ---------------------------------------------------------------------------
__device__ __forceinline__ unsigned pack_half2(float a, float b) {
    __half2 h = __floats2half2_rn(a, b);
    return *(unsigned*)&h;
}

__device__ __forceinline__ unsigned hex2(float a, float b) {
    // (a,b) -> half2 -> 2^x elementwise (approx)
    unsigned r;
    __half2 h = __floats2half2_rn(a, b);
    asm("ex2.approx.f16x2 %0, %1;\n" : "=r"(r) : "r"(*(unsigned*)&h));
    return r;
}

__device__ __forceinline__ void mma_fp16(
    float* d, const unsigned* a, const unsigned* b, const float* c)
{
    asm volatile(
        "mma.sync.aligned.m16n8k16.row.col.f32.f16.f16.f32 "
        "{%0,%1,%2,%3}, {%4,%5,%6,%7}, {%8,%9}, {%10,%11,%12,%13};\n"
        : "=f"(d[0]), "=f"(d[1]), "=f"(d[2]), "=f"(d[3])
        : "r"(a[0]), "r"(a[1]), "r"(a[2]), "r"(a[3]),
          "r"(b[0]), "r"(b[1]),
          "f"(c[0]), "f"(c[1]), "f"(c[2]), "f"(c[3]));
}

__device__ __forceinline__ void ldsm_x4(unsigned* r, unsigned addr) {
    asm volatile(
        "ldmatrix.sync.aligned.m8n8.x4.shared.b16 {%0,%1,%2,%3}, [%4];\n"
        : "=r"(r[0]), "=r"(r[1]), "=r"(r[2]), "=r"(r[3]) : "r"(addr));
}

__device__ __forceinline__ void cp_async16(void* smem_ptr, const void* gmem_ptr) {
    unsigned saddr = (unsigned)__cvta_generic_to_shared(smem_ptr);
    asm volatile("cp.async.cg.shared.global [%0], [%1], 16;\n"
                 :: "r"(saddr), "l"(gmem_ptr));
}
__device__ __forceinline__ void cp_commit() {
    asm volatile("cp.async.commit_group;\n");
}
template<int N> __device__ __forceinline__ void cp_wait() {
    asm volatile("cp.async.wait_group %0;\n" :: "n"(N));
}

// ---------------------------------------------------------------------------
// cvt x -> fp16 (identity layout)
// ---------------------------------------------------------------------------
__global__ __launch_bounds__(256) void cvt_x_fp16(
    const float* __restrict__ x, __half* __restrict__ xh)
{
    int i = blockIdx.x * 256 + threadIdx.x;
    float4 v0 = *(const float4*)&x[(size_t)i * 8];
    float4 v1 = *(const float4*)&x[(size_t)i * 8 + 4];
    uint4 u;
    u.x = pack_half2(v0.x, v0.y);
    u.y = pack_half2(v0.z, v0.w);
    u.z = pack_half2(v1.x, v1.y);
    u.w = pack_half2(v1.z, v1.w);
    *(uint4*)&xh[(size_t)i * 8] = u;
}

// ---------------------------------------------------------------------------
// transpose + cvt weights: W[k][n] fp32 -> WT[n][k] fp16
// ---------------------------------------------------------------------------
__global__ __launch_bounds__(256) void cvt_w_t(
    const float* __restrict__ wq, const float* __restrict__ wk,
    const float* __restrict__ wv, const float* __restrict__ wo)
{
    __shared__ __half tile[32][33];
    const float* W; __half* WT;
    if (blockIdx.z == 0)      { W = wq; WT = g_Wqh; }
    else if (blockIdx.z == 1) { W = wk; WT = g_Wkh; }
    else if (blockIdx.z == 2) { W = wv; WT = g_Wvh; }
    else                      { W = wo; WT = g_Woh; }

    int tx = threadIdx.x, ty = threadIdx.y;
    int bx = blockIdx.x * 32, by = blockIdx.y * 32;
    #pragma unroll
    for (int j = 0; j < 4; j++) {
        int r = by + ty + j * 8;
        tile[ty + j * 8][tx] = __float2half(W[(size_t)r * DMODEL + bx + tx]);
    }
    __syncthreads();
    #pragma unroll
    for (int j = 0; j < 4; j++) {
        int r = bx + ty + j * 8;
        WT[(size_t)r * DMODEL + by + tx] = tile[tx][ty + j * 8];
    }
}

// ---------------------------------------------------------------------------
// fp16 GEMM with ldmatrix fragment loads, cp.async double-buffered.
// (unchanged from R11)
// ---------------------------------------------------------------------------
#define GW 20
#define GEMM_SMEM_WORDS (2 * 128 * GW * 2)
#define GEMM_SMEM_BYTES (GEMM_SMEM_WORDS * 4)

__global__ __launch_bounds__(256) void gemm_fp16_bias_relu(
    const __half* __restrict__ A,
    const __half* __restrict__ W0, const float* __restrict__ b0, void* __restrict__ C0,
    const __half* __restrict__ W1, const float* __restrict__ b1, void* __restrict__ C1,
    const __half* __restrict__ W2, const float* __restrict__ b2, void* __restrict__ C2,
    int modeSel)
{
    const int N = 1024, K = 1024;
    extern __shared__ unsigned smg[];
    unsigned* As = smg;                  // [2][128][20]
    unsigned* Bs = smg + 2 * 128 * GW;   // [2][128][20]

    const __half* W; const float* bias; void* C;
    if (blockIdx.z == 0)      { W = W0; bias = b0; C = C0; }
    else if (blockIdx.z == 1) { W = W1; bias = b1; C = C1; }
    else                      { W = W2; bias = b2; C = C2; }
    int mode = modeSel ? ((blockIdx.z == 2) ? 2 : 1) : 0;

    int tid  = threadIdx.x;
    int lane = tid & 31;
    int warp = tid >> 5;
    int gid  = lane >> 2;
    int tig  = lane & 3;
    int l8   = lane & 7;
    int tile = lane >> 3;

    int m0w = (warp & 1) * 64;
    int n0w = (warp >> 1) * 32;

    int rowBase = blockIdx.y * 128;
    int colBase = blockIdx.x * 128;

    unsigned smem_u = (unsigned)__cvta_generic_to_shared(smg);
    unsigned as_u = smem_u;
    unsigned bs_u = smem_u + 2 * 128 * GW * 4;
    unsigned aoff = (((tile & 1) * 8 + l8) * GW + (tile >> 1) * 4) * 4;
    unsigned boff = (((tile >> 1) * 8 + l8) * GW + (tile & 1) * 4) * 4;

    float acc[4][4][4] = {};

    {
        #pragma unroll
        for (int v = 0; v < 2; v++) {
            int idx = tid + v * 256;
            int r = idx >> 2, cw = (idx & 3) * 4;
            cp_async16(&As[(size_t)r * GW + cw], &A[(size_t)(rowBase + r) * K + cw * 2]);
            cp_async16(&Bs[(size_t)r * GW + cw], &W[(size_t)(colBase + r) * K + cw * 2]);
        }
        cp_commit();
    }

    #pragma unroll 1
    for (int it = 0; it < 32; it++) {
        int buf = it & 1;
        if (it + 1 < 32) {
            int k0n = (it + 1) * 32;
            unsigned* An = As + (buf ^ 1) * 128 * GW;
            unsigned* Bn = Bs + (buf ^ 1) * 128 * GW;
            #pragma unroll
            for (int v = 0; v < 2; v++) {
                int idx = tid + v * 256;
                int r = idx >> 2, cw = (idx & 3) * 4;
                cp_async16(&An[(size_t)r * GW + cw],
                           &A[(size_t)(rowBase + r) * K + k0n + cw * 2]);
                cp_async16(&Bn[(size_t)r * GW + cw],
                           &W[(size_t)(colBase + r) * K + k0n + cw * 2]);
            }
            cp_commit();
            cp_wait<1>();
        } else {
            cp_wait<0>();
        }
        __syncthreads();

        unsigned ab_u = as_u + buf * 128 * GW * 4;
        unsigned bb_u = bs_u + buf * 128 * GW * 4;

        #pragma unroll
        for (int ks = 0; ks < 2; ks++) {
            unsigned af[4][4], bf[2][4];
            #pragma unroll
            for (int mt = 0; mt < 4; mt++)
                ldsm_x4(af[mt], ab_u + (((m0w + mt * 16) * GW + ks * 8) * 4) + aoff);
            ldsm_x4(bf[0], bb_u + (((n0w     ) * GW + ks * 8) * 4) + boff);
            ldsm_x4(bf[1], bb_u + (((n0w + 16) * GW + ks * 8) * 4) + boff);
            #pragma unroll
            for (int mt = 0; mt < 4; mt++) {
                mma_fp16(acc[mt][0], af[mt], &bf[0][0], acc[mt][0]);
                mma_fp16(acc[mt][1], af[mt], &bf[0][2], acc[mt][1]);
                mma_fp16(acc[mt][2], af[mt], &bf[1][0], acc[mt][2]);
                mma_fp16(acc[mt][3], af[mt], &bf[1][2], acc[mt][3]);
            }
        }
        __syncthreads();
    }

    #pragma unroll
    for (int mt = 0; mt < 4; mt++) {
        #pragma unroll
        for (int nt = 0; nt < 4; nt++) {
            int col = colBase + n0w + nt * 8 + tig * 2;
            float bv0 = bias[col], bv1 = bias[col + 1];
            int r0 = rowBase + m0w + mt * 16 + gid;
            float v00 = fmaxf(acc[mt][nt][0] + bv0, 0.f);
            float v01 = fmaxf(acc[mt][nt][1] + bv1, 0.f);
            float v10 = fmaxf(acc[mt][nt][2] + bv0, 0.f);
            float v11 = fmaxf(acc[mt][nt][3] + bv1, 0.f);
            if (mode == 0) {
                float* Cf = (float*)C;
                float2 o0, o1;
                o0.x = v00; o0.y = v01;
                o1.x = v10; o1.y = v11;
                *(float2*)&Cf[(size_t)r0 * N + col]       = o0;
                *(float2*)&Cf[(size_t)(r0 + 8) * N + col] = o1;
            } else if (mode == 1) {
                unsigned* Cw = (unsigned*)C;
                Cw[((size_t)r0 * N + col) >> 1]       = pack_half2(v00, v01);
                Cw[((size_t)(r0 + 8) * N + col) >> 1] = pack_half2(v10, v11);
            } else {
                __half* VT = (__half*)C;
                int b = r0 >> 11, s = r0 & 2047;
                int h = col >> 6, d = col & 63;
                size_t base = ((size_t)(b * NHEAD + h) * DHEAD + d) * SEQ + s;
                VT[base]            = __float2half(v00);
                VT[base + SEQ]      = __float2half(v01);
                VT[base + 8]        = __float2half(v10);
                VT[base + SEQ + 8]  = __float2half(v11);
            }
        }
    }
}

// ---------------------------------------------------------------------------
// fp16 flash attention v3: no-max softmax (scores >= 0, shift-invariant,
// exactly matches reference semantics incl. masked->exp(0)=1), P kept in
// registers (S-accumulator frag == PV A-frag), row-sum l computed by the
// tensor core via a constant all-ones B fragment, exp via ex2.approx.f16x2,
// mask via ballots. CTA = 128 q x 1 head x 1 batch, 128 thr = 4 warps,
// warp owns 32 q rows. cp.async double-buffered K/V/mask.
// ---------------------------------------------------------------------------
#define ATW 36
#define AT_K_WORDS  (2 * 64 * ATW)
#define AT_V_WORDS  (2 * 64 * ATW)
#define AT_SMEM_BYTES ((AT_K_WORDS + AT_V_WORDS + 2 * 64) * 4)

__global__ __launch_bounds__(128) void attention_mma(
    const __half* __restrict__ Q, const __half* __restrict__ K,
    const __half* __restrict__ VT, const int* __restrict__ mask,
    __half* __restrict__ O)
{
    extern __shared__ unsigned sm[];
    unsigned* Ks  = sm;                        // [2][64][36]
    unsigned* Vs  = Ks + AT_K_WORDS;           // [2][64][36]
    int*      mk  = (int*)(Vs + AT_V_WORDS);   // [2][64]

    int tid  = threadIdx.x;
    int lane = tid & 31;
    int warp = tid >> 5;
    int gid  = lane >> 2;
    int tig  = lane & 3;
    int l8   = lane & 7;
    int tile = lane >> 3;
    int qt = blockIdx.x;
    int h  = blockIdx.y;
    int b  = blockIdx.z;
    int qbase = qt * 128;
    int m0 = warp * 32;
    const float SCL2E = 0.125f * 1.4426950408889634f;   // scale * log2(e)

    const size_t headOff = (size_t)h * DHEAD;
    const size_t bRow = (size_t)b * SEQ;
    const __half* VTh = VT + (size_t)(b * NHEAD + h) * DHEAD * SEQ;

    unsigned smem_u = (unsigned)__cvta_generic_to_shared(sm);
    unsigned ks_u = smem_u;
    unsigned vs_u = smem_u + AT_K_WORDS * 4;
    unsigned boff = (((tile >> 1) * 8 + l8) * ATW + (tile & 1) * 4) * 4;

    // constant all-ones B fragment (B n-index = groupID): column n=0 is ones
    unsigned bones = (gid == 0) ? 0x3C003C00u : 0u;
    unsigned bf_ones[2] = {bones, bones};

    // --- Q fragments ---
    unsigned qf[2][4][4];
    {
        const unsigned* Qw = (const unsigned*)(Q + (bRow + qbase + m0) * DMODEL + headOff);
        #pragma unroll
        for (int mt = 0; mt < 2; mt++) {
            #pragma unroll
            for (int kt = 0; kt < 4; kt++) {
                size_t r0 = (size_t)(mt * 16 + gid) * 512;
                size_t r1 = (size_t)(mt * 16 + gid + 8) * 512;
                qf[mt][kt][0] = Qw[r0 + kt * 8 + tig];
                qf[mt][kt][1] = Qw[r1 + kt * 8 + tig];
                qf[mt][kt][2] = Qw[r0 + kt * 8 + tig + 4];
                qf[mt][kt][3] = Qw[r1 + kt * 8 + tig + 4];
            }
        }
    }

    // --- issue chunk 0 ---
    {
        #pragma unroll
        for (int v = 0; v < 4; v++) {
            int idx = tid + v * 128;
            int row = idx >> 3, cw = (idx & 7) * 4;
            cp_async16(&Ks[(size_t)row * ATW + cw],
                       &K[(bRow + row) * DMODEL + headOff + cw * 2]);
            cp_async16(&Vs[(size_t)row * ATW + cw],
                       &VTh[(size_t)row * SEQ + cw * 2]);
        }
        if (tid < 16) cp_async16(&mk[tid * 4], &mask[bRow + tid * 4]);
        cp_commit();
    }

    float oacc[2][8][4] = {};
    float lacc[2][4] = {};      // l accumulators via ones-column mma

    #pragma unroll 1
    for (int kc = 0; kc < SEQ / 64; kc++) {
        int buf = kc & 1;
        if (kc + 1 < SEQ / 64) {
            int nb = buf ^ 1;
            unsigned* Kn = Ks + nb * 64 * ATW;
            unsigned* Vn = Vs + nb * 64 * ATW;
            #pragma unroll
            for (int v = 0; v < 4; v++) {
                int idx = tid + v * 128;
                int row = idx >> 3, cw = (idx & 7) * 4;
                cp_async16(&Kn[(size_t)row * ATW + cw],
                           &K[(bRow + (kc + 1) * 64 + row) * DMODEL + headOff + cw * 2]);
                cp_async16(&Vn[(size_t)row * ATW + cw],
                           &VTh[(size_t)row * SEQ + (kc + 1) * 64 + cw * 2]);
            }
            if (tid < 16)
                cp_async16(&mk[nb * 64 + tid * 4],
                           &mask[bRow + (kc + 1) * 64 + tid * 4]);
            cp_commit();
            cp_wait<1>();
        } else {
            cp_wait<0>();
        }
        __syncthreads();

        unsigned kb_u = ks_u + buf * 64 * ATW * 4;
        unsigned vb_u = vs_u + buf * 64 * ATW * 4;
        int* mkb = mk + buf * 64;

        // mask bits for this chunk (2 LDS + 2 ballots)
        unsigned mlo = __ballot_sync(0xffffffffu, mkb[lane] != 0);
        unsigned mhi = __ballot_sync(0xffffffffu, mkb[lane + 32] != 0);

        // --- S = Q K^T ---
        float s[2][8][4] = {};
        #pragma unroll
        for (int kt = 0; kt < 4; kt++) {
            #pragma unroll
            for (int j = 0; j < 4; j++) {
                unsigned bq[4];
                ldsm_x4(bq, kb_u + ((j * 16 * ATW + kt * 8) * 4) + boff);
                mma_fp16(s[0][2*j],     qf[0][kt], &bq[0], s[0][2*j]);
                mma_fp16(s[1][2*j],     qf[1][kt], &bq[0], s[1][2*j]);
                mma_fp16(s[0][2*j + 1], qf[0][kt], &bq[2], s[0][2*j + 1]);
                mma_fp16(s[1][2*j + 1], qf[1][kt], &bq[2], s[1][2*j + 1]);
            }
        }

        // --- P = exp2(s * scale * log2e), masked -> exp(0)=1 ; P stays in regs ---
        unsigned pf[2][8][2];
        #pragma unroll
        for (int nt = 0; nt < 8; nt++) {
            int c0 = nt * 8 + 2 * tig;
            unsigned mw = (nt < 4) ? mlo : mhi;
            bool k0m = (mw >> (c0 & 31)) & 1;
            bool k1m = (mw >> ((c0 + 1) & 31)) & 1;
            #pragma unroll
            for (int mt = 0; mt < 2; mt++) {
                float t0 = k0m ? 0.f : s[mt][nt][0] * SCL2E;
                float t1 = k1m ? 0.f : s[mt][nt][1] * SCL2E;
                float t2 = k0m ? 0.f : s[mt][nt][2] * SCL2E;
                float t3 = k1m ? 0.f : s[mt][nt][3] * SCL2E;
                pf[mt][nt][0] = hex2(t0, t1);   // rows gid   : k=2tig,2tig+1
                pf[mt][nt][1] = hex2(t2, t3);   // rows gid+8
            }
        }

        // --- O += P V (P already in A-frag layout) + l via ones column ---
        #pragma unroll
        for (int kk = 0; kk < 4; kk++) {
            unsigned af0[4] = { pf[0][2*kk][0], pf[0][2*kk][1],
                                pf[0][2*kk+1][0], pf[0][2*kk+1][1] };
            unsigned af1[4] = { pf[1][2*kk][0], pf[1][2*kk][1],
                                pf[1][2*kk+1][0], pf[1][2*kk+1][1] };
            #pragma unroll
            for (int j = 0; j < 4; j++) {
                unsigned bv[4];
                ldsm_x4(bv, vb_u + ((j * 16 * ATW + kk * 8) * 4) + boff);
                mma_fp16(oacc[0][2*j],     af0, &bv[0], oacc[0][2*j]);
                mma_fp16(oacc[1][2*j],     af1, &bv[0], oacc[1][2*j]);
                mma_fp16(oacc[0][2*j + 1], af0, &bv[2], oacc[0][2*j + 1]);
                mma_fp16(oacc[1][2*j + 1], af1, &bv[2], oacc[1][2*j + 1]);
            }
            mma_fp16(lacc[0], af0, bf_ones, lacc[0]);
            mma_fp16(lacc[1], af1, bf_ones, lacc[1]);
        }
        __syncthreads();   // K/V buffers reused by next iter's cp.async
    }

    // --- epilogue: fetch l (col 0 lives on tig==0 lanes), normalize, store ---
    unsigned* Ow = (unsigned*)O;
    #pragma unroll
    for (int mt = 0; mt < 2; mt++) {
        float l0 = __shfl_sync(0xffffffffu, lacc[mt][0], lane & 0x1c);
        float l1 = __shfl_sync(0xffffffffu, lacc[mt][2], lane & 0x1c);
        float inv0 = 1.f / l0;
        float inv1 = 1.f / l1;
        size_t r0 = ((bRow + qbase + m0 + mt * 16 + gid) * DMODEL + headOff) >> 1;
        size_t r1 = ((bRow + qbase + m0 + mt * 16 + gid + 8) * DMODEL + headOff) >> 1;
        #pragma unroll
        for (int dt = 0; dt < 8; dt++) {
            int cw = dt * 4 + tig;
            Ow[r0 + cw] = pack_half2(oacc[mt][dt][0] * inv0, oacc[mt][dt][1] * inv0);
            Ow[r1 + cw] = pack_half2(oacc[mt][dt][2] * inv1, oacc[mt][dt][3] * inv1);
        }
    }
}

// ---------------------------------------------------------------------------
// launch
// ---------------------------------------------------------------------------
extern "C" void kernel_launch(void* const* d_in, const int* in_sizes, int n_in,
                              void* d_out, int out_size)
{
    const float* x    = (const float*)d_in[0];
    const int*   mask = (const int*)  d_in[1];
    const float* Wq   = (const float*)d_in[2];
    const float* bq   = (const float*)d_in[3];
    const float* Wk   = (const float*)d_in[4];
    const float* bk   = (const float*)d_in[5];
    const float* Wv   = (const float*)d_in[6];
    const float* bv   = (const float*)d_in[7];
    const float* Wo   = (const float*)d_in[8];
    const float* bo   = (const float*)d_in[9];
    float* out = (float*)d_out;

    __half *xh, *Wqh, *Wkh, *Wvh, *Woh, *Qp, *Kp, *Vp, *AOp;
    cudaGetSymbolAddress((void**)&xh,  g_xh);
    cudaGetSymbolAddress((void**)&Wqh, g_Wqh);
    cudaGetSymbolAddress((void**)&Wkh, g_Wkh);
    cudaGetSymbolAddress((void**)&Wvh, g_Wvh);
    cudaGetSymbolAddress((void**)&Woh, g_Woh);
    cudaGetSymbolAddress((void**)&Qp,  g_Q);
    cudaGetSymbolAddress((void**)&Kp,  g_K);
    cudaGetSymbolAddress((void**)&Vp,  g_V);
    cudaGetSymbolAddress((void**)&AOp, g_AO);

    cudaFuncSetAttribute(gemm_fp16_bias_relu,
                         cudaFuncAttributeMaxDynamicSharedMemorySize, GEMM_SMEM_BYTES);
    cudaFuncSetAttribute(attention_mma,
                         cudaFuncAttributeMaxDynamicSharedMemorySize, AT_SMEM_BYTES);

    // convert inputs
    cvt_x_fp16<<<MROWS * DMODEL / 8 / 256, 256>>>(x, xh);
    cvt_w_t<<<dim3(32, 32, 4), dim3(32, 8)>>>(Wq, Wk, Wv, Wo);

    // fused Q/K/V projections (Q,K natural fp16; V transposed fp16)
    dim3 gqkv(1024 / 128, 4096 / 128, 3);
    gemm_fp16_bias_relu<<<gqkv, 256, GEMM_SMEM_BYTES>>>(xh,
                                       Wqh, bq, Qp,
                                       Wkh, bk, Kp,
                                       Wvh, bv, Vp, 1);

    attention_mma<<<dim3(SEQ / 128, NHEAD, BATCH), 128, AT_SMEM_BYTES>>>(
        Qp, Kp, Vp, mask, AOp);

    // output projection (fp32 store)
    dim3 go(1024 / 128, 4096 / 128, 1);
    gemm_fp16_bias_relu<<<go, 256, GEMM_SMEM_BYTES>>>(AOp,
                                     Woh, bo, out,
                                     Woh, bo, out,
                                     Woh, bo, out, 0);
}